// round 4
// baseline (speedup 1.0000x reference)
#include <cuda_runtime.h>
#include <cuda_bf16.h>
#include <math.h>

// ---------------- problem constants ----------------
#define BATCH 128
#define SPAT  121          // H*W = d_spectral (dg)
#define DM    128          // d_model
#define DI    256          // d_inner = scan length L
#define NST   16           // d_state
#define RTK   8            // dt_rank
#define C40   40           // dt_rank + 2*NST
#define ROWS  (BATCH*SPAT) // 15488
#define BL    (BATCH*DI)   // 32768 rows for per-(b,l) GEMMs

// ---------------- scratch (device globals; no allocation allowed) ----------------
__device__ float g_xz  [ROWS*512];          // in_proj output [b*121+s][512]
__device__ float g_u   [BL*SPAT];           // conv+silu out, [b][l][dg]
__device__ float g_xdbl[2ull*BL*C40];       // x_dbl per dir  [k][b*256+l][40]
__device__ float g_delta[2ull*BL*SPAT];     // softplus dt    [k][b*256+l][dg]
__device__ float g_ys  [2ull*BL*SPAT];      // scan out       [k][b*256+l][dg]
__device__ float g_ygT [ROWS*DI];           // LN*gelu(z)     [b*121+dg][l]

// ---------------- generic f32 GEMM: C[r][c] = sum_k A[r][k]*W[c][k] ----------------
// M must be multiple of 64. N,K arbitrary (guarded). ACT=1: softplus(x+bias[c]).
template<int ACT>
__global__ void __launch_bounds__(256) gemm_kernel(
    const float* __restrict__ A, const float* __restrict__ W,
    const float* __restrict__ bias, float* __restrict__ C,
    int M, int N, int K, int lda, int ldb, int ldc)
{
    const int BM = 64, BN = 64, BK = 16;
    __shared__ __align__(16) float As[BK][BM + 4];  // [16][68]
    __shared__ __align__(16) float Ws[BK][BN + 4];

    int t  = threadIdx.x;
    int tx = t & 15, ty = t >> 4;
    int rowBase = blockIdx.x * BM;
    int colBase = blockIdx.y * BN;

    float acc[4][4];
#pragma unroll
    for (int i = 0; i < 4; i++)
#pragma unroll
        for (int j = 0; j < 4; j++) acc[i][j] = 0.f;

    for (int k0 = 0; k0 < K; k0 += BK) {
#pragma unroll
        for (int j = 0; j < 4; j++) {
            int idx = t + j * 256;          // 0..1023
            int r = idx >> 4, kk = idx & 15;
            int gk = k0 + kk;
            As[kk][r] = (gk < K) ? A[(size_t)(rowBase + r) * lda + gk] : 0.f;
            int c = r;
            Ws[kk][c] = (gk < K && (colBase + c) < N)
                        ? W[(size_t)(colBase + c) * ldb + gk] : 0.f;
        }
        __syncthreads();
#pragma unroll
        for (int kk = 0; kk < BK; kk++) {
            float4 a = *(const float4*)&As[kk][ty * 4];
            float4 b = *(const float4*)&Ws[kk][tx * 4];
            acc[0][0] += a.x * b.x; acc[0][1] += a.x * b.y; acc[0][2] += a.x * b.z; acc[0][3] += a.x * b.w;
            acc[1][0] += a.y * b.x; acc[1][1] += a.y * b.y; acc[1][2] += a.y * b.z; acc[1][3] += a.y * b.w;
            acc[2][0] += a.z * b.x; acc[2][1] += a.z * b.y; acc[2][2] += a.z * b.z; acc[2][3] += a.z * b.w;
            acc[3][0] += a.w * b.x; acc[3][1] += a.w * b.y; acc[3][2] += a.w * b.z; acc[3][3] += a.w * b.w;
        }
        __syncthreads();
    }

#pragma unroll
    for (int i = 0; i < 4; i++) {
        int r = rowBase + ty * 4 + i;
#pragma unroll
        for (int j = 0; j < 4; j++) {
            int c = colBase + tx * 4 + j;
            if (c < N) {
                float v = acc[i][j];
                if (ACT == 1) {
                    v += bias[c];
                    v = (v > 20.f) ? v : log1pf(expf(v));   // softplus
                }
                C[(size_t)r * ldc + c] = v;
            }
        }
    }
}

// ---------------- depthwise 3x3 conv + SiLU, xz[:, :256] -> u[b][l][dg] ----------------
__global__ void __launch_bounds__(256) conv_kernel(
    const float* __restrict__ xz, const float* __restrict__ conv_w,
    const float* __restrict__ conv_b, float* __restrict__ u)
{
    __shared__ float s_in[SPAT * 65];
    int ct = blockIdx.x;           // 0..3 -> 64-channel chunk
    int b  = blockIdx.y;
    int t  = threadIdx.x;

    for (int idx = t; idx < SPAT * 64; idx += 256) {
        int s = idx >> 6, c = idx & 63;
        s_in[s * 65 + c] = xz[((size_t)b * SPAT + s) * 512 + ct * 64 + c];
    }
    __syncthreads();

    size_t base = ((size_t)b * DI + ct * 64) * SPAT;
    for (int idx = t; idx < 64 * SPAT; idx += 256) {
        int c = idx / SPAT;
        int s = idx - c * SPAT;
        int i = s / 11, j = s - i * 11;
        int ch = ct * 64 + c;
        float acc = conv_b[ch];
#pragma unroll
        for (int ti = 0; ti < 3; ti++) {
            int ii = i + ti - 1;
            if ((unsigned)ii < 11u) {
#pragma unroll
                for (int tj = 0; tj < 3; tj++) {
                    int jj = j + tj - 1;
                    if ((unsigned)jj < 11u)
                        acc += s_in[(ii * 11 + jj) * 65 + c] * conv_w[ch * 9 + ti * 3 + tj];
                }
            }
        }
        float sv = acc / (1.f + __expf(-acc));   // SiLU
        u[base + idx] = sv;                      // idx == c*121 + s, coalesced
    }
}

// ---------------- selective scan: thread per (b,k,dg), 16 states in regs ----------------
__global__ void __launch_bounds__(32) scan_kernel(
    const float* __restrict__ delta, const float* __restrict__ xdbl,
    const float* __restrict__ u, const float* __restrict__ A_logs,
    const float* __restrict__ Ds, float* __restrict__ ys)
{
    __shared__ float sB[16][16];
    __shared__ float sC[16][16];

    int b  = blockIdx.x;
    int k  = blockIdx.y;
    int dg = blockIdx.z * 32 + threadIdx.x;
    bool act = dg < SPAT;

    float a[NST], hh[NST], Dv = 0.f;
#pragma unroll
    for (int n = 0; n < NST; n++) hh[n] = 0.f;
    if (act) {
        const float* arow = A_logs + ((size_t)k * SPAT + dg) * NST;
#pragma unroll
        for (int n = 0; n < NST; n++) a[n] = -expf(arow[n]);
        Dv = Ds[k * SPAT + dg];
    } else {
#pragma unroll
        for (int n = 0; n < NST; n++) a[n] = 0.f;
    }

    const float* dptr = delta + ((size_t)k * BL + (size_t)b * DI) * SPAT + dg;
    const float* uptr = u     + ((size_t)b * DI) * SPAT + dg;
    float*       yptr = ys    + ((size_t)k * BL + (size_t)b * DI) * SPAT + dg;
    const float* xd   = xdbl  + ((size_t)k * BL + (size_t)b * DI) * C40;

    for (int l0 = 0; l0 < DI; l0 += 16) {
        __syncthreads();
        for (int idx = threadIdx.x; idx < 256; idx += 32) {
            int i = idx >> 4, n = idx & 15;
            const float* rp = xd + (size_t)(l0 + i) * C40;
            sB[i][n] = rp[RTK + n];
            sC[i][n] = rp[RTK + NST + n];
        }
        __syncthreads();
        if (act) {
#pragma unroll 4
            for (int i = 0; i < 16; i++) {
                int l = l0 + i;
                float d  = dptr[(size_t)l * SPAT];
                float uv = uptr[(size_t)l * SPAT];
                float du = d * uv;
                float y  = 0.f;
#pragma unroll
                for (int n = 0; n < NST; n++) {
                    float e = __expf(d * a[n]);
                    hh[n] = e * hh[n] + du * sB[i][n];
                    y += hh[n] * sC[i][n];
                }
                yptr[(size_t)l * SPAT] = y + Dv * uv;
            }
        }
    }
}

// ---------------- combine dirs + LayerNorm(dg) + gelu(z) gate; write [b][dg][l] ----------------
__global__ void __launch_bounds__(256) ln_kernel(
    const float* __restrict__ ys, const float* __restrict__ xz,
    const float* __restrict__ ln_g, const float* __restrict__ ln_b,
    float* __restrict__ ygT)
{
    __shared__ float tY[64 * 129];
    __shared__ float s_mu[64], s_rs[64];

    int lt = blockIdx.x;     // 64-wide l tile (0..3)
    int b  = blockIdx.y;
    int t  = threadIdx.x;

    const float* ysA = ys + ((size_t)b * DI + lt * 64) * SPAT;
    const float* ysB = ys + (size_t)BL * SPAT + (size_t)b * DI * SPAT;

    for (int idx = t; idx < 64 * SPAT; idx += 256) {
        int l = idx / SPAT, dg = idx - l * SPAT;
        int gl = lt * 64 + l;
        float v = ysA[(size_t)l * SPAT + dg] + ysB[(size_t)(255 - gl) * SPAT + dg];
        tY[l * 129 + dg] = v;
    }
    __syncthreads();

    int w = t >> 5, lane = t & 31;
    for (int l = w * 8; l < w * 8 + 8; l++) {
        float s1 = 0.f, s2 = 0.f;
        for (int dg = lane; dg < SPAT; dg += 32) {
            float v = tY[l * 129 + dg];
            s1 += v; s2 += v * v;
        }
#pragma unroll
        for (int off = 16; off > 0; off >>= 1) {
            s1 += __shfl_xor_sync(0xffffffffu, s1, off);
            s2 += __shfl_xor_sync(0xffffffffu, s2, off);
        }
        if (lane == 0) {
            float mu = s1 * (1.f / SPAT);
            float var = s2 * (1.f / SPAT) - mu * mu;
            s_mu[l] = mu;
            s_rs[l] = rsqrtf(var + 1e-5f);
        }
    }
    __syncthreads();

    for (int idx = t; idx < SPAT * 64; idx += 256) {
        int dg = idx >> 6, l = idx & 63;
        int gl = lt * 64 + l;
        float v = (tY[l * 129 + dg] - s_mu[l]) * s_rs[l] * ln_g[dg] + ln_b[dg];
        float zv = xz[((size_t)b * SPAT + dg) * 512 + 256 + gl];
        float gz = 0.5f * zv * (1.f + erff(zv * 0.7071067811865475f));
        ygT[((size_t)b * SPAT + dg) * DI + gl] = v * gz;
    }
}

// ---------------- launcher ----------------
extern "C" void kernel_launch(void* const* d_in, const int* in_sizes, int n_in,
                              void* d_out, int out_size)
{
    const float* x         = (const float*)d_in[0];
    const float* in_proj_w = (const float*)d_in[1];
    const float* conv_w    = (const float*)d_in[2];
    const float* conv_b    = (const float*)d_in[3];
    const float* x_proj_w  = (const float*)d_in[4];
    const float* dt_proj_w = (const float*)d_in[5];
    const float* dt_proj_b = (const float*)d_in[6];
    const float* A_logs    = (const float*)d_in[7];
    const float* Ds        = (const float*)d_in[8];
    const float* ln_g      = (const float*)d_in[9];
    const float* ln_b      = (const float*)d_in[10];
    const float* out_proj_w= (const float*)d_in[11];
    float* out = (float*)d_out;

    float *p_xz, *p_u, *p_xdbl, *p_delta, *p_ys, *p_ygT;
    cudaGetSymbolAddress((void**)&p_xz,   g_xz);
    cudaGetSymbolAddress((void**)&p_u,    g_u);
    cudaGetSymbolAddress((void**)&p_xdbl, g_xdbl);
    cudaGetSymbolAddress((void**)&p_delta,g_delta);
    cudaGetSymbolAddress((void**)&p_ys,   g_ys);
    cudaGetSymbolAddress((void**)&p_ygT,  g_ygT);

    // K1: xz = x @ in_proj_w.T   [15488,128]x[512,128]
    gemm_kernel<0><<<dim3(ROWS / 64, 512 / 64), 256>>>(
        x, in_proj_w, nullptr, p_xz, ROWS, 512, DM, DM, DM, 512);

    // K2: depthwise conv + SiLU -> u[b][l][dg]
    conv_kernel<<<dim3(4, BATCH), 256>>>(p_xz, conv_w, conv_b, p_u);

    // K3a: x_dbl_k = u @ x_proj_w[k].T   [32768,121]x[40,121]
    for (int k = 0; k < 2; k++)
        gemm_kernel<0><<<dim3(BL / 64, 1), 256>>>(
            p_u, x_proj_w + (size_t)k * C40 * SPAT, nullptr,
            p_xdbl + (size_t)k * BL * C40, BL, C40, SPAT, SPAT, SPAT, C40);

    // K3b: delta_k = softplus(dts @ dt_proj_w[k].T + b)   [32768,8]x[121,8]
    for (int k = 0; k < 2; k++)
        gemm_kernel<1><<<dim3(BL / 64, 2), 256>>>(
            p_xdbl + (size_t)k * BL * C40, dt_proj_w + (size_t)k * SPAT * RTK,
            dt_proj_b + (size_t)k * SPAT,
            p_delta + (size_t)k * BL * SPAT, BL, SPAT, RTK, C40, RTK, SPAT);

    // K4: selective scan
    scan_kernel<<<dim3(BATCH, 2, 4), 32>>>(p_delta, p_xdbl, p_u, A_logs, Ds, p_ys);

    // K5: combine directions + LN + gelu(z) gate
    ln_kernel<<<dim3(4, BATCH), 256>>>(p_ys, p_xz, ln_g, ln_b, p_ygT);

    // K6: out = ygT @ out_proj_w.T   [15488,256]x[128,256]
    gemm_kernel<0><<<dim3(ROWS / 64, 2), 256>>>(
        p_ygT, out_proj_w, nullptr, out, ROWS, DM, DI, DI, DI, DM);
}

// round 6
// speedup vs baseline: 1.3496x; 1.3496x over previous
#include <cuda_runtime.h>
#include <cuda_bf16.h>
#include <math.h>

// ---------------- problem constants ----------------
#define BATCH 128
#define SPAT  121          // H*W = d_spectral (dg)
#define DM    128          // d_model
#define DI    256          // d_inner = scan length L
#define NST   16           // d_state
#define RTK   8            // dt_rank
#define C40   40           // dt_rank + 2*NST per direction
#define C80   80           // merged both directions
#define ROWS  (BATCH*SPAT) // 15488
#define BL    (BATCH*DI)   // 32768 rows for per-(b,l) GEMMs

// ---------------- scratch (device globals; no allocation allowed) ----------------
__device__ float g_xz   [ROWS*512];          // in_proj output [b*121+s][512]
__device__ float g_u    [BL*SPAT];           // conv+silu out, [b][l][dg]
__device__ float g_xdbl2[(size_t)BL*C80];    // merged x_dbl   [b*256+l][80] (k*40+{dt8,B16,C16})
__device__ float g_delta[2ull*BL*SPAT];      // softplus dt    [k][b*256+l][dg]
__device__ float g_ys   [2ull*BL*SPAT];      // scan out       [k][b*256+l][dg]
__device__ float g_ygT  [ROWS*DI];           // LN*gelu(z)     [b*121+dg][l]

// ---------------- f32 GEMM: C[r][c] = sum_k A[r][k]*W[c][k] ----------------
// BM=128, BN=128, BK=16; 256 threads, 8x8 micro-tile, double-buffered smem.
// Requires M % 128 == 0 (true for all call sites). N,K arbitrary (guarded).
// ACT=1: softplus(x + bias[c]).
template<int ACT>
__global__ void __launch_bounds__(256) gemm128(
    const float* __restrict__ A, const float* __restrict__ W,
    const float* __restrict__ bias, float* __restrict__ C,
    int N, int K, int lda, int ldb, int ldc)
{
    const int BK = 16;
    __shared__ __align__(16) float As[2][BK][128 + 4];
    __shared__ __align__(16) float Bs[2][BK][128 + 4];

    const int t  = threadIdx.x;
    const int tx = t & 15, ty = t >> 4;          // 16 x 16 thread grid
    const int rowBase = blockIdx.x * 128;
    const int colBase = blockIdx.y * 128;

    float acc[8][8];
#pragma unroll
    for (int i = 0; i < 8; i++)
#pragma unroll
        for (int j = 0; j < 8; j++) acc[i][j] = 0.f;

    const int nk = (K + BK - 1) / BK;

    // ---- load tile 0 into buffer 0 ----
#pragma unroll
    for (int j = 0; j < 8; j++) {
        int idx = t + j * 256;                   // 0..2047
        int r = idx >> 4, kk = idx & 15;         // r: row/col in tile, kk: k
        As[0][kk][r] = (kk < K) ? A[(size_t)(rowBase + r) * lda + kk] : 0.f;
        Bs[0][kk][r] = (kk < K && colBase + r < N)
                       ? W[(size_t)(colBase + r) * ldb + kk] : 0.f;
    }
    __syncthreads();

    for (int kt = 0; kt < nk; kt++) {
        const int buf = kt & 1;
        float ra[8], rb[8];
        const bool more = (kt + 1 < nk);
        if (more) {
            int k0 = (kt + 1) * BK;
#pragma unroll
            for (int j = 0; j < 8; j++) {
                int idx = t + j * 256;
                int r = idx >> 4, kk = idx & 15;
                int gk = k0 + kk;
                ra[j] = (gk < K) ? A[(size_t)(rowBase + r) * lda + gk] : 0.f;
                rb[j] = (gk < K && colBase + r < N)
                        ? W[(size_t)(colBase + r) * ldb + gk] : 0.f;
            }
        }

#pragma unroll
        for (int kk = 0; kk < BK; kk++) {
            float av[8], bv[8];
            *(float4*)&av[0] = *(const float4*)&As[buf][kk][ty * 8];
            *(float4*)&av[4] = *(const float4*)&As[buf][kk][ty * 8 + 4];
            *(float4*)&bv[0] = *(const float4*)&Bs[buf][kk][tx * 8];
            *(float4*)&bv[4] = *(const float4*)&Bs[buf][kk][tx * 8 + 4];
#pragma unroll
            for (int i = 0; i < 8; i++)
#pragma unroll
                for (int j = 0; j < 8; j++)
                    acc[i][j] += av[i] * bv[j];
        }

        if (more) {
#pragma unroll
            for (int j = 0; j < 8; j++) {
                int idx = t + j * 256;
                int r = idx >> 4, kk = idx & 15;
                As[buf ^ 1][kk][r] = ra[j];
                Bs[buf ^ 1][kk][r] = rb[j];
            }
            __syncthreads();
        }
    }

#pragma unroll
    for (int i = 0; i < 8; i++) {
        size_t r = (size_t)(rowBase + ty * 8 + i);
#pragma unroll
        for (int j = 0; j < 8; j++) {
            int c = colBase + tx * 8 + j;
            if (c < N) {
                float v = acc[i][j];
                if (ACT == 1) {
                    v += bias[c];
                    v = (v > 20.f) ? v : log1pf(expf(v));   // softplus
                }
                C[r * ldc + c] = v;
            }
        }
    }
}

// ---------------- depthwise 3x3 conv + SiLU, xz[:, :256] -> u[b][l][dg] ----------------
__global__ void __launch_bounds__(256) conv_kernel(
    const float* __restrict__ xz, const float* __restrict__ conv_w,
    const float* __restrict__ conv_b, float* __restrict__ u)
{
    __shared__ float s_in[SPAT * 65];
    int ct = blockIdx.x;           // 0..3 -> 64-channel chunk
    int b  = blockIdx.y;
    int t  = threadIdx.x;

    for (int idx = t; idx < SPAT * 64; idx += 256) {
        int s = idx >> 6, c = idx & 63;
        s_in[s * 65 + c] = xz[((size_t)b * SPAT + s) * 512 + ct * 64 + c];
    }
    __syncthreads();

    size_t base = ((size_t)b * DI + ct * 64) * SPAT;
    for (int idx = t; idx < 64 * SPAT; idx += 256) {
        int c = idx / SPAT;
        int s = idx - c * SPAT;
        int i = s / 11, j = s - i * 11;
        int ch = ct * 64 + c;
        float acc = conv_b[ch];
#pragma unroll
        for (int ti = 0; ti < 3; ti++) {
            int ii = i + ti - 1;
            if ((unsigned)ii < 11u) {
#pragma unroll
                for (int tj = 0; tj < 3; tj++) {
                    int jj = j + tj - 1;
                    if ((unsigned)jj < 11u)
                        acc += s_in[(ii * 11 + jj) * 65 + c] * conv_w[ch * 9 + ti * 3 + tj];
                }
            }
        }
        float sv = acc / (1.f + __expf(-acc));   // SiLU
        u[base + idx] = sv;                      // idx == c*121 + s, coalesced
    }
}

// ---------------- selective scan: grid (b, k), 128 threads (dg), states in regs ----------------
__global__ void __launch_bounds__(128) scan_kernel(
    const float* __restrict__ delta, const float* __restrict__ xdbl2,
    const float* __restrict__ u, const float* __restrict__ A_logs,
    const float* __restrict__ Ds, float* __restrict__ ys)
{
    __shared__ float sB[16][16];
    __shared__ float sC[16][16];

    int b  = blockIdx.x;
    int k  = blockIdx.y;
    int dg = threadIdx.x;
    bool act = dg < SPAT;

    float a[NST], hh[NST], Dv = 0.f;
#pragma unroll
    for (int n = 0; n < NST; n++) hh[n] = 0.f;
    if (act) {
        const float* arow = A_logs + ((size_t)k * SPAT + dg) * NST;
#pragma unroll
        for (int n = 0; n < NST; n++) a[n] = -expf(arow[n]);
        Dv = Ds[k * SPAT + dg];
    } else {
#pragma unroll
        for (int n = 0; n < NST; n++) a[n] = 0.f;
    }

    const float* dptr = delta + ((size_t)k * BL + (size_t)b * DI) * SPAT + dg;
    const float* uptr = u     + ((size_t)b * DI) * SPAT + dg;
    float*       yptr = ys    + ((size_t)k * BL + (size_t)b * DI) * SPAT + dg;
    const float* xd   = xdbl2 + ((size_t)b * DI) * C80 + k * C40;

    for (int l0 = 0; l0 < DI; l0 += 16) {
        __syncthreads();
        for (int idx = threadIdx.x; idx < 256; idx += 128) {
            int i = idx >> 4, n = idx & 15;
            const float* rp = xd + (size_t)(l0 + i) * C80;
            sB[i][n] = rp[RTK + n];
            sC[i][n] = rp[RTK + NST + n];
        }
        __syncthreads();
        if (act) {
#pragma unroll 4
            for (int i = 0; i < 16; i++) {
                int l = l0 + i;
                float d  = dptr[(size_t)l * SPAT];
                float uv = uptr[(size_t)l * SPAT];
                float du = d * uv;
                float y  = 0.f;
#pragma unroll
                for (int n = 0; n < NST; n++) {
                    float e = __expf(d * a[n]);
                    hh[n] = e * hh[n] + du * sB[i][n];
                    y += hh[n] * sC[i][n];
                }
                yptr[(size_t)l * SPAT] = y + Dv * uv;
            }
        }
    }
}

// ---------------- combine dirs + LayerNorm(dg) + gelu(z) gate; write [b][dg][l] ----------------
__global__ void __launch_bounds__(256) ln_kernel(
    const float* __restrict__ ys, const float* __restrict__ xz,
    const float* __restrict__ ln_g, const float* __restrict__ ln_b,
    float* __restrict__ ygT)
{
    __shared__ float tY[64 * 129];
    __shared__ float s_mu[64], s_rs[64];

    int lt = blockIdx.x;     // 64-wide l tile (0..3)
    int b  = blockIdx.y;
    int t  = threadIdx.x;

    const float* ysA = ys + ((size_t)b * DI + lt * 64) * SPAT;
    const float* ysB = ys + (size_t)BL * SPAT + (size_t)b * DI * SPAT;

    for (int idx = t; idx < 64 * SPAT; idx += 256) {
        int l = idx / SPAT, dg = idx - l * SPAT;
        int gl = lt * 64 + l;
        float v = ysA[(size_t)l * SPAT + dg] + ysB[(size_t)(255 - gl) * SPAT + dg];
        tY[l * 129 + dg] = v;
    }
    __syncthreads();

    int w = t >> 5, lane = t & 31;
    for (int l = w * 8; l < w * 8 + 8; l++) {
        float s1 = 0.f, s2 = 0.f;
        for (int dg = lane; dg < SPAT; dg += 32) {
            float v = tY[l * 129 + dg];
            s1 += v; s2 += v * v;
        }
#pragma unroll
        for (int off = 16; off > 0; off >>= 1) {
            s1 += __shfl_xor_sync(0xffffffffu, s1, off);
            s2 += __shfl_xor_sync(0xffffffffu, s2, off);
        }
        if (lane == 0) {
            float mu = s1 * (1.f / SPAT);
            float var = s2 * (1.f / SPAT) - mu * mu;
            s_mu[l] = mu;
            s_rs[l] = rsqrtf(var + 1e-5f);
        }
    }
    __syncthreads();

    for (int idx = t; idx < SPAT * 64; idx += 256) {
        int dg = idx >> 6, l = idx & 63;
        int gl = lt * 64 + l;
        float v = (tY[l * 129 + dg] - s_mu[l]) * s_rs[l] * ln_g[dg] + ln_b[dg];
        float zv = xz[((size_t)b * SPAT + dg) * 512 + 256 + gl];
        float gz = 0.5f * zv * (1.f + erff(zv * 0.7071067811865475f));
        ygT[((size_t)b * SPAT + dg) * DI + gl] = v * gz;
    }
}

// ---------------- launcher ----------------
extern "C" void kernel_launch(void* const* d_in, const int* in_sizes, int n_in,
                              void* d_out, int out_size)
{
    const float* x         = (const float*)d_in[0];
    const float* in_proj_w = (const float*)d_in[1];
    const float* conv_w    = (const float*)d_in[2];
    const float* conv_b    = (const float*)d_in[3];
    const float* x_proj_w  = (const float*)d_in[4];   // [2,40,121] == [80,121]
    const float* dt_proj_w = (const float*)d_in[5];   // [2,121,8]
    const float* dt_proj_b = (const float*)d_in[6];   // [2,121]
    const float* A_logs    = (const float*)d_in[7];
    const float* Ds        = (const float*)d_in[8];
    const float* ln_g      = (const float*)d_in[9];
    const float* ln_b      = (const float*)d_in[10];
    const float* out_proj_w= (const float*)d_in[11];
    float* out = (float*)d_out;

    float *p_xz, *p_u, *p_xdbl2, *p_delta, *p_ys, *p_ygT;
    cudaGetSymbolAddress((void**)&p_xz,    g_xz);
    cudaGetSymbolAddress((void**)&p_u,     g_u);
    cudaGetSymbolAddress((void**)&p_xdbl2, g_xdbl2);
    cudaGetSymbolAddress((void**)&p_delta, g_delta);
    cudaGetSymbolAddress((void**)&p_ys,    g_ys);
    cudaGetSymbolAddress((void**)&p_ygT,   g_ygT);

    // K1: xz = x @ in_proj_w.T   [15488,128] x [512,128]^T
    gemm128<0><<<dim3(ROWS / 128, 512 / 128), 256>>>(
        x, in_proj_w, nullptr, p_xz, 512, DM, DM, DM, 512);

    // K2: depthwise conv + SiLU -> u[b][l][dg]
    conv_kernel<<<dim3(4, BATCH), 256>>>(p_xz, conv_w, conv_b, p_u);

    // K3a: merged x_dbl for both dirs: [32768,121] x [80,121]^T -> [32768,80]
    gemm128<0><<<dim3(BL / 128, 1), 256>>>(
        p_u, x_proj_w, nullptr, p_xdbl2, C80, SPAT, SPAT, SPAT, C80);

    // K3b: delta_k = softplus(dts_k @ dt_proj_w[k].T + b_k)  [32768,8] x [121,8]^T
    for (int k = 0; k < 2; k++)
        gemm128<1><<<dim3(BL / 128, 1), 256>>>(
            p_xdbl2 + k * C40, dt_proj_w + (size_t)k * SPAT * RTK,
            dt_proj_b + (size_t)k * SPAT,
            p_delta + (size_t)k * BL * SPAT, SPAT, RTK, C80, RTK, SPAT);

    // K4: selective scan
    scan_kernel<<<dim3(BATCH, 2), 128>>>(p_delta, p_xdbl2, p_u, A_logs, Ds, p_ys);

    // K5: combine directions + LN + gelu(z) gate -> ygT[b*121+dg][l]
    ln_kernel<<<dim3(4, BATCH), 256>>>(p_ys, p_xz, ln_g, ln_b, p_ygT);

    // K6: out = ygT @ out_proj_w.T   [15488,256] x [128,256]^T
    gemm128<0><<<dim3(ROWS / 128, 1), 256>>>(
        p_ygT, out_proj_w, nullptr, out, DM, DI, DI, DI, DM);
}

// round 9
// speedup vs baseline: 1.5021x; 1.1129x over previous
#include <cuda_runtime.h>
#include <cuda_bf16.h>
#include <math.h>

// ---------------- problem constants ----------------
#define BATCH 128
#define SPAT  121          // H*W = d_spectral (dg)
#define DM    128          // d_model
#define DI    256          // d_inner = scan length L
#define NST   16           // d_state
#define RTK   8            // dt_rank
#define C40   40           // dt_rank + 2*NST per direction
#define C80   80           // merged both directions
#define ROWS  (BATCH*SPAT) // 15488
#define BL    (BATCH*DI)   // 32768 rows for per-(b,l) GEMMs

// ---------------- scratch (device globals; no allocation allowed) ----------------
__device__ float g_xz   [ROWS*512];          // in_proj output [b*121+s][512]
__device__ float g_u    [BL*SPAT];           // conv+silu out, [b][l][dg]
__device__ float g_xdbl2[(size_t)BL*C80];    // merged x_dbl   [b*256+l][80] (k*40+{dt8,B16,C16})
__device__ float g_ys   [2ull*BL*SPAT];      // scan out       [k][b*256+l][dg]
__device__ float g_ygT  [ROWS*DI];           // LN*gelu(z)     [b*121+dg][l]

// ---------------- f32 GEMM: C[r][c] = sum_k A[r][k]*W[c][k] ----------------
// BM=128, BN=128, BK=16; 256 threads, 8x8 micro-tile, double-buffered smem.
// Requires M % 128 == 0 (true for all call sites). N,K arbitrary (guarded).
__global__ void __launch_bounds__(256) gemm128(
    const float* __restrict__ A, const float* __restrict__ W,
    float* __restrict__ C,
    int N, int K, int lda, int ldb, int ldc)
{
    const int BK = 16;
    __shared__ __align__(16) float As[2][BK][128 + 4];
    __shared__ __align__(16) float Bs[2][BK][128 + 4];

    const int t  = threadIdx.x;
    const int tx = t & 15, ty = t >> 4;          // 16 x 16 thread grid
    const int rowBase = blockIdx.x * 128;
    const int colBase = blockIdx.y * 128;

    float acc[8][8];
#pragma unroll
    for (int i = 0; i < 8; i++)
#pragma unroll
        for (int j = 0; j < 8; j++) acc[i][j] = 0.f;

    const int nk = (K + BK - 1) / BK;

    // ---- load tile 0 into buffer 0 ----
#pragma unroll
    for (int j = 0; j < 8; j++) {
        int idx = t + j * 256;                   // 0..2047
        int r = idx >> 4, kk = idx & 15;         // r: row/col in tile, kk: k
        As[0][kk][r] = (kk < K) ? A[(size_t)(rowBase + r) * lda + kk] : 0.f;
        Bs[0][kk][r] = (kk < K && colBase + r < N)
                       ? W[(size_t)(colBase + r) * ldb + kk] : 0.f;
    }
    __syncthreads();

    for (int kt = 0; kt < nk; kt++) {
        const int buf = kt & 1;
        float ra[8], rb[8];
        const bool more = (kt + 1 < nk);
        if (more) {
            int k0 = (kt + 1) * BK;
#pragma unroll
            for (int j = 0; j < 8; j++) {
                int idx = t + j * 256;
                int r = idx >> 4, kk = idx & 15;
                int gk = k0 + kk;
                ra[j] = (gk < K) ? A[(size_t)(rowBase + r) * lda + gk] : 0.f;
                rb[j] = (gk < K && colBase + r < N)
                        ? W[(size_t)(colBase + r) * ldb + gk] : 0.f;
            }
        }

#pragma unroll
        for (int kk = 0; kk < BK; kk++) {
            float av[8], bv[8];
            *(float4*)&av[0] = *(const float4*)&As[buf][kk][ty * 8];
            *(float4*)&av[4] = *(const float4*)&As[buf][kk][ty * 8 + 4];
            *(float4*)&bv[0] = *(const float4*)&Bs[buf][kk][tx * 8];
            *(float4*)&bv[4] = *(const float4*)&Bs[buf][kk][tx * 8 + 4];
#pragma unroll
            for (int i = 0; i < 8; i++)
#pragma unroll
                for (int j = 0; j < 8; j++)
                    acc[i][j] += av[i] * bv[j];
        }

        if (more) {
#pragma unroll
            for (int j = 0; j < 8; j++) {
                int idx = t + j * 256;
                int r = idx >> 4, kk = idx & 15;
                As[buf ^ 1][kk][r] = ra[j];
                Bs[buf ^ 1][kk][r] = rb[j];
            }
            __syncthreads();
        }
    }

#pragma unroll
    for (int i = 0; i < 8; i++) {
        size_t r = (size_t)(rowBase + ty * 8 + i);
#pragma unroll
        for (int j = 0; j < 8; j++) {
            int c = colBase + tx * 8 + j;
            if (c < N) C[r * ldc + c] = acc[i][j];
        }
    }
}

// ---------------- depthwise 3x3 conv + SiLU, xz[:, :256] -> u[b][l][dg] ----------------
__global__ void __launch_bounds__(256) conv_kernel(
    const float* __restrict__ xz, const float* __restrict__ conv_w,
    const float* __restrict__ conv_b, float* __restrict__ u)
{
    __shared__ float s_in[SPAT * 65];
    int ct = blockIdx.x;           // 0..3 -> 64-channel chunk
    int b  = blockIdx.y;
    int t  = threadIdx.x;

    for (int idx = t; idx < SPAT * 64; idx += 256) {
        int s = idx >> 6, c = idx & 63;
        s_in[s * 65 + c] = xz[((size_t)b * SPAT + s) * 512 + ct * 64 + c];
    }
    __syncthreads();

    size_t base = ((size_t)b * DI + ct * 64) * SPAT;
    for (int idx = t; idx < 64 * SPAT; idx += 256) {
        int c = idx / SPAT;
        int s = idx - c * SPAT;
        int i = s / 11, j = s - i * 11;
        int ch = ct * 64 + c;
        float acc = conv_b[ch];
#pragma unroll
        for (int ti = 0; ti < 3; ti++) {
            int ii = i + ti - 1;
            if ((unsigned)ii < 11u) {
#pragma unroll
                for (int tj = 0; tj < 3; tj++) {
                    int jj = j + tj - 1;
                    if ((unsigned)jj < 11u)
                        acc += s_in[(ii * 11 + jj) * 65 + c] * conv_w[ch * 9 + ti * 3 + tj];
                }
            }
        }
        float sv = acc / (1.f + __expf(-acc));   // SiLU
        u[base + idx] = sv;                      // idx == c*121 + s, coalesced
    }
}

// ---------------- selective scan (fused dt-proj + softplus + scan) ----------------
// grid (b, k), 128 threads (dg lane). delta computed in-register from x_dbl;
// exp(d*a[n]) via single exp + power tree when A has the geometric structure
// a[n] = (n+1)*a[0] (runtime-checked; generic fallback otherwise).
__global__ void __launch_bounds__(128) scan_kernel(
    const float* __restrict__ xdbl2, const float* __restrict__ u,
    const float* __restrict__ dt_proj_w, const float* __restrict__ dt_proj_b,
    const float* __restrict__ A_logs, const float* __restrict__ Ds,
    float* __restrict__ ys)
{
    __shared__ float sDT[16][RTK];
    __shared__ float sB[16][16];
    __shared__ float sC[16][16];

    const int b  = blockIdx.x;
    const int k  = blockIdx.y;
    const int dg = threadIdx.x;
    const bool act = dg < SPAT;

    float aG[NST], hh[NST], w8[RTK];
    float a1 = 0.f, bias = 0.f, Dv = 0.f;
    bool geo = false;
#pragma unroll
    for (int n = 0; n < NST; n++) { hh[n] = 0.f; aG[n] = 0.f; }
#pragma unroll
    for (int r = 0; r < RTK; r++) w8[r] = 0.f;

    if (act) {
        const float* arow = A_logs + ((size_t)k * SPAT + dg) * NST;
        a1 = -expf(arow[0]);
        geo = true;
#pragma unroll
        for (int n = 0; n < NST; n++) {
            aG[n] = -expf(arow[n]);
            float tgt = (float)(n + 1) * a1;
            if (fabsf(aG[n] - tgt) > 1e-5f * (float)(n + 1) * fabsf(a1)) geo = false;
        }
        Dv = Ds[k * SPAT + dg];
        const float* wrow = dt_proj_w + ((size_t)k * SPAT + dg) * RTK;
#pragma unroll
        for (int r = 0; r < RTK; r++) w8[r] = wrow[r];
        bias = dt_proj_b[k * SPAT + dg];
    }

    const float* uptr = u  + ((size_t)b * DI) * SPAT + dg;
    float*       yptr = ys + ((size_t)k * BL + (size_t)b * DI) * SPAT + dg;
    const float* xd   = xdbl2 + ((size_t)b * DI) * C80 + k * C40;

    for (int l0 = 0; l0 < DI; l0 += 16) {
        __syncthreads();
        for (int idx = threadIdx.x; idx < 16 * C40; idx += 128) {
            int i = idx / C40, c = idx - i * C40;
            float v = __ldg(&xd[(size_t)(l0 + i) * C80 + c]);
            if (c < RTK)            sDT[i][c] = v;
            else if (c < RTK + NST) sB[i][c - RTK] = v;
            else                    sC[i][c - RTK - NST] = v;
        }
        __syncthreads();
        if (act) {
#pragma unroll 4
            for (int i = 0; i < 16; i++) {
                int l = l0 + i;
                float dr = bias;
#pragma unroll
                for (int r = 0; r < RTK; r++) dr = fmaf(w8[r], sDT[i][r], dr);
                float d = (dr > 20.f) ? dr : log1pf(__expf(dr));
                float uv = __ldg(&uptr[(size_t)l * SPAT]);
                float du = d * uv;
                float y  = 0.f;
                if (geo) {
                    float p1 = __expf(d * a1);
                    float p2 = p1 * p1, p3 = p2 * p1, p4 = p2 * p2;
                    float p5 = p4 * p1, p6 = p4 * p2, p7 = p4 * p3, p8 = p4 * p4;
                    float e[NST] = { p1, p2, p3, p4, p5, p6, p7, p8,
                                     p8 * p1, p8 * p2, p8 * p3, p8 * p4,
                                     p8 * p5, p8 * p6, p8 * p7, p8 * p8 };
#pragma unroll
                    for (int n = 0; n < NST; n++) {
                        hh[n] = e[n] * hh[n] + du * sB[i][n];
                        y += hh[n] * sC[i][n];
                    }
                } else {
#pragma unroll
                    for (int n = 0; n < NST; n++) {
                        float e = __expf(d * aG[n]);
                        hh[n] = e * hh[n] + du * sB[i][n];
                        y += hh[n] * sC[i][n];
                    }
                }
                yptr[(size_t)l * SPAT] = y + Dv * uv;
            }
        }
    }
}

// ---------------- combine dirs + LayerNorm(dg) + gelu(z) gate; write [b][dg][l] ----------------
__global__ void __launch_bounds__(256) ln_kernel(
    const float* __restrict__ ys, const float* __restrict__ xz,
    const float* __restrict__ ln_g, const float* __restrict__ ln_b,
    float* __restrict__ ygT)
{
    __shared__ float tY[64 * 129];
    __shared__ float s_mu[64], s_rs[64];

    int lt = blockIdx.x;     // 64-wide l tile (0..3)
    int b  = blockIdx.y;
    int t  = threadIdx.x;

    const float* ysA = ys + ((size_t)b * DI + lt * 64) * SPAT;
    const float* ysB = ys + (size_t)BL * SPAT + (size_t)b * DI * SPAT;

    for (int idx = t; idx < 64 * SPAT; idx += 256) {
        int l = idx / SPAT, dg = idx - l * SPAT;
        int gl = lt * 64 + l;
        float v = ysA[(size_t)l * SPAT + dg] + ysB[(size_t)(255 - gl) * SPAT + dg];
        tY[l * 129 + dg] = v;
    }
    __syncthreads();

    int w = t >> 5, lane = t & 31;
    for (int l = w * 8; l < w * 8 + 8; l++) {
        float s1 = 0.f, s2 = 0.f;
        for (int dg = lane; dg < SPAT; dg += 32) {
            float v = tY[l * 129 + dg];
            s1 += v; s2 += v * v;
        }
#pragma unroll
        for (int off = 16; off > 0; off >>= 1) {
            s1 += __shfl_xor_sync(0xffffffffu, s1, off);
            s2 += __shfl_xor_sync(0xffffffffu, s2, off);
        }
        if (lane == 0) {
            float mu = s1 * (1.f / SPAT);
            float var = s2 * (1.f / SPAT) - mu * mu;
            s_mu[l] = mu;
            s_rs[l] = rsqrtf(var + 1e-5f);
        }
    }
    __syncthreads();

    for (int idx = t; idx < SPAT * 64; idx += 256) {
        int dg = idx >> 6, l = idx & 63;
        int gl = lt * 64 + l;
        float v = (tY[l * 129 + dg] - s_mu[l]) * s_rs[l] * ln_g[dg] + ln_b[dg];
        float zv = xz[((size_t)b * SPAT + dg) * 512 + 256 + gl];
        float gz = 0.5f * zv * (1.f + erff(zv * 0.7071067811865475f));
        ygT[((size_t)b * SPAT + dg) * DI + gl] = v * gz;
    }
}

// ---------------- launcher ----------------
extern "C" void kernel_launch(void* const* d_in, const int* in_sizes, int n_in,
                              void* d_out, int out_size)
{
    const float* x         = (const float*)d_in[0];
    const float* in_proj_w = (const float*)d_in[1];
    const float* conv_w    = (const float*)d_in[2];
    const float* conv_b    = (const float*)d_in[3];
    const float* x_proj_w  = (const float*)d_in[4];   // [2,40,121] == [80,121]
    const float* dt_proj_w = (const float*)d_in[5];   // [2,121,8]
    const float* dt_proj_b = (const float*)d_in[6];   // [2,121]
    const float* A_logs    = (const float*)d_in[7];
    const float* Ds        = (const float*)d_in[8];
    const float* ln_g      = (const float*)d_in[9];
    const float* ln_b      = (const float*)d_in[10];
    const float* out_proj_w= (const float*)d_in[11];
    float* out = (float*)d_out;

    float *p_xz, *p_u, *p_xdbl2, *p_ys, *p_ygT;
    cudaGetSymbolAddress((void**)&p_xz,    g_xz);
    cudaGetSymbolAddress((void**)&p_u,     g_u);
    cudaGetSymbolAddress((void**)&p_xdbl2, g_xdbl2);
    cudaGetSymbolAddress((void**)&p_ys,    g_ys);
    cudaGetSymbolAddress((void**)&p_ygT,   g_ygT);

    // K1: xz = x @ in_proj_w.T   [15488,128] x [512,128]^T
    gemm128<<<dim3(ROWS / 128, 512 / 128), 256>>>(
        x, in_proj_w, p_xz, 512, DM, DM, DM, 512);

    // K2: depthwise conv + SiLU -> u[b][l][dg]
    conv_kernel<<<dim3(4, BATCH), 256>>>(p_xz, conv_w, conv_b, p_u);

    // K3: merged x_dbl for both dirs: [32768,121] x [80,121]^T -> [32768,80]
    gemm128<<<dim3(BL / 128, 1), 256>>>(
        p_u, x_proj_w, p_xdbl2, C80, SPAT, SPAT, SPAT, C80);

    // K4: selective scan (dt-proj + softplus fused in)
    scan_kernel<<<dim3(BATCH, 2), 128>>>(
        p_xdbl2, p_u, dt_proj_w, dt_proj_b, A_logs, Ds, p_ys);

    // K5: combine directions + LN + gelu(z) gate -> ygT[b*121+dg][l]
    ln_kernel<<<dim3(4, BATCH), 256>>>(p_ys, p_xz, ln_g, ln_b, p_ygT);

    // K6: out = ygT @ out_proj_w.T   [15488,256] x [128,256]^T
    gemm128<<<dim3(ROWS / 128, 1), 256>>>(
        p_ygT, out_proj_w, out, DM, DI, DI, DI, DM);
}

// round 10
// speedup vs baseline: 1.6910x; 1.1258x over previous
#include <cuda_runtime.h>
#include <cuda_bf16.h>
#include <math.h>

// ---------------- problem constants ----------------
#define BATCH 128
#define SPAT  121          // H*W = d_spectral (dg)
#define DM    128          // d_model
#define DI    256          // d_inner = scan length L
#define NST   16           // d_state
#define RTK   8            // dt_rank
#define C40   40           // dt_rank + 2*NST per direction
#define C80   80           // merged both directions
#define ROWS  (BATCH*SPAT) // 15488
#define BL    (BATCH*DI)   // 32768 rows for per-(b,l) GEMMs

#define NCHUNK 4
#define LCHUNK (DI/NCHUNK) // 64

// dynamic smem layout for scan (floats):
//   sDT [256*8]   @ 0
//   sB  [256*16]  @ 2048
//   sC  [256*16]  @ 6144
//   sH  [4*121*17]@ 10240   (pad 17 -> conflict-free)
//   sS  [4*128]   @ 18468
#define SCAN_SMEM_FLOATS (18468 + 512)
#define SCAN_SMEM_BYTES  (SCAN_SMEM_FLOATS * 4)

// ---------------- scratch (device globals; no allocation allowed) ----------------
__device__ float g_xz   [ROWS*512];          // in_proj output [b*121+s][512]
__device__ float g_u    [BL*SPAT];           // conv+silu out, [b][l][dg]
__device__ float g_xdbl2[(size_t)BL*C80];    // merged x_dbl   [b*256+l][80]
__device__ float g_ys   [2ull*BL*SPAT];      // scan out       [k][b*256+l][dg]
__device__ float g_ygT  [ROWS*DI];           // LN*gelu(z)     [b*121+dg][l]

// ---------------- f32 GEMM: C[r][c] = sum_k A[r][k]*W[c][k] ----------------
__global__ void __launch_bounds__(256) gemm128(
    const float* __restrict__ A, const float* __restrict__ W,
    float* __restrict__ C,
    int N, int K, int lda, int ldb, int ldc)
{
    const int BK = 16;
    __shared__ __align__(16) float As[2][BK][128 + 4];
    __shared__ __align__(16) float Bs[2][BK][128 + 4];

    const int t  = threadIdx.x;
    const int tx = t & 15, ty = t >> 4;
    const int rowBase = blockIdx.x * 128;
    const int colBase = blockIdx.y * 128;

    float acc[8][8];
#pragma unroll
    for (int i = 0; i < 8; i++)
#pragma unroll
        for (int j = 0; j < 8; j++) acc[i][j] = 0.f;

    const int nk = (K + BK - 1) / BK;

#pragma unroll
    for (int j = 0; j < 8; j++) {
        int idx = t + j * 256;
        int r = idx >> 4, kk = idx & 15;
        As[0][kk][r] = (kk < K) ? A[(size_t)(rowBase + r) * lda + kk] : 0.f;
        Bs[0][kk][r] = (kk < K && colBase + r < N)
                       ? W[(size_t)(colBase + r) * ldb + kk] : 0.f;
    }
    __syncthreads();

    for (int kt = 0; kt < nk; kt++) {
        const int buf = kt & 1;
        float ra[8], rb[8];
        const bool more = (kt + 1 < nk);
        if (more) {
            int k0 = (kt + 1) * BK;
#pragma unroll
            for (int j = 0; j < 8; j++) {
                int idx = t + j * 256;
                int r = idx >> 4, kk = idx & 15;
                int gk = k0 + kk;
                ra[j] = (gk < K) ? A[(size_t)(rowBase + r) * lda + gk] : 0.f;
                rb[j] = (gk < K && colBase + r < N)
                        ? W[(size_t)(colBase + r) * ldb + gk] : 0.f;
            }
        }

#pragma unroll
        for (int kk = 0; kk < BK; kk++) {
            float av[8], bv[8];
            *(float4*)&av[0] = *(const float4*)&As[buf][kk][ty * 8];
            *(float4*)&av[4] = *(const float4*)&As[buf][kk][ty * 8 + 4];
            *(float4*)&bv[0] = *(const float4*)&Bs[buf][kk][tx * 8];
            *(float4*)&bv[4] = *(const float4*)&Bs[buf][kk][tx * 8 + 4];
#pragma unroll
            for (int i = 0; i < 8; i++)
#pragma unroll
                for (int j = 0; j < 8; j++)
                    acc[i][j] += av[i] * bv[j];
        }

        if (more) {
#pragma unroll
            for (int j = 0; j < 8; j++) {
                int idx = t + j * 256;
                int r = idx >> 4, kk = idx & 15;
                As[buf ^ 1][kk][r] = ra[j];
                Bs[buf ^ 1][kk][r] = rb[j];
            }
            __syncthreads();
        }
    }

#pragma unroll
    for (int i = 0; i < 8; i++) {
        size_t r = (size_t)(rowBase + ty * 8 + i);
#pragma unroll
        for (int j = 0; j < 8; j++) {
            int c = colBase + tx * 8 + j;
            if (c < N) C[r * ldc + c] = acc[i][j];
        }
    }
}

// ---------------- depthwise 3x3 conv + SiLU, xz[:, :256] -> u[b][l][dg] ----------------
__global__ void __launch_bounds__(256) conv_kernel(
    const float* __restrict__ xz, const float* __restrict__ conv_w,
    const float* __restrict__ conv_b, float* __restrict__ u)
{
    __shared__ float s_in[SPAT * 65];
    int ct = blockIdx.x;
    int b  = blockIdx.y;
    int t  = threadIdx.x;

    for (int idx = t; idx < SPAT * 64; idx += 256) {
        int s = idx >> 6, c = idx & 63;
        s_in[s * 65 + c] = xz[((size_t)b * SPAT + s) * 512 + ct * 64 + c];
    }
    __syncthreads();

    size_t base = ((size_t)b * DI + ct * 64) * SPAT;
    for (int idx = t; idx < 64 * SPAT; idx += 256) {
        int c = idx / SPAT;
        int s = idx - c * SPAT;
        int i = s / 11, j = s - i * 11;
        int ch = ct * 64 + c;
        float acc = conv_b[ch];
#pragma unroll
        for (int ti = 0; ti < 3; ti++) {
            int ii = i + ti - 1;
            if ((unsigned)ii < 11u) {
#pragma unroll
                for (int tj = 0; tj < 3; tj++) {
                    int jj = j + tj - 1;
                    if ((unsigned)jj < 11u)
                        acc += s_in[(ii * 11 + jj) * 65 + c] * conv_w[ch * 9 + ti * 3 + tj];
                }
            }
        }
        float sv = acc / (1.f + __expf(-acc));
        u[base + idx] = sv;
    }
}

// ---------------- chunk-parallel selective scan ----------------
// block = (b,k), 512 threads: c = tid>>7 (chunk 0..3), dg = tid&127.
// Phase A: chunks 0..2 local scan (h0=0), record h_end + S=sum(delta).
// Combine: 3-step prefix over chunk ends (chunk decay = exp(a_n * S)).
// Phase C: all chunks full scan seeded with true h0, write y.
__device__ __forceinline__ float softplus_f(float x) {
    return (x > 20.f) ? x : log1pf(__expf(x));
}

// multiply hh by per-state decay from exponent base q=exp(a1*s) (geo) or
// exp(arow[n]*s) (generic); optionally also do the full step update.
__global__ void __launch_bounds__(512, 2) scan_kernel(
    const float* __restrict__ xdbl2, const float* __restrict__ u,
    const float* __restrict__ dt_proj_w, const float* __restrict__ dt_proj_b,
    const float* __restrict__ A_logs, const float* __restrict__ Ds,
    float* __restrict__ ys)
{
    extern __shared__ float sm[];
    float* sDT = sm;            // [l*8+r]
    float* sB  = sm + 2048;     // [l*16+n]
    float* sC  = sm + 6144;     // [l*16+n]
    float* sH  = sm + 10240;    // [(c*121+dg)*17+n]
    float* sS  = sm + 18468;    // [c*128+dg]

    const int b   = blockIdx.x;
    const int k   = blockIdx.y;
    const int tid = threadIdx.x;
    const int c   = tid >> 7;
    const int dg  = tid & 127;
    const bool act = dg < SPAT;

    // ---- stage x_dbl slice [256][40] for this (b,k) ----
    const float* xd = xdbl2 + ((size_t)b * DI) * C80 + k * C40;
    for (int idx = tid; idx < DI * C40; idx += 512) {
        int l = idx / C40, cc = idx - l * C40;
        float v = __ldg(&xd[(size_t)l * C80 + cc]);
        if (cc < RTK)            sDT[l * RTK + cc] = v;
        else if (cc < RTK + NST) sB[l * NST + (cc - RTK)] = v;
        else                     sC[l * NST + (cc - RTK - NST)] = v;
    }

    // ---- per-(k,dg) parameters ----
    float w8[RTK];
    float a1 = 0.f, bias = 0.f, Dv = 0.f;
    bool geo = false;
    const float* arow = A_logs + ((size_t)k * SPAT + (act ? dg : 0)) * NST;
    if (act) {
        a1 = -expf(arow[0]);
        geo = true;
#pragma unroll
        for (int n = 0; n < NST; n++) {
            float an = -expf(arow[n]);
            float tgt = (float)(n + 1) * a1;
            if (fabsf(an - tgt) > 1e-5f * (float)(n + 1) * fabsf(a1)) geo = false;
        }
        Dv = Ds[k * SPAT + dg];
        const float* wrow = dt_proj_w + ((size_t)k * SPAT + dg) * RTK;
#pragma unroll
        for (int r = 0; r < RTK; r++) w8[r] = wrow[r];
        bias = dt_proj_b[k * SPAT + dg];
    }
    __syncthreads();

    const float* uptr = u + ((size_t)b * DI) * SPAT + dg;
    const int l_beg = c * LCHUNK;

    // ---- Phase A: local scan, chunks 0..2 ----
    if (act && c < NCHUNK - 1) {
        float hh[NST];
#pragma unroll
        for (int n = 0; n < NST; n++) hh[n] = 0.f;
        float S = 0.f;
        for (int l = l_beg; l < l_beg + LCHUNK; l++) {
            float dr = bias;
#pragma unroll
            for (int r = 0; r < RTK; r++) dr = fmaf(w8[r], sDT[l * RTK + r], dr);
            float d = softplus_f(dr);
            S += d;
            float du = d * __ldg(&uptr[(size_t)l * SPAT]);
            if (geo) {
                float p1 = __expf(d * a1);
                float p2 = p1 * p1, p4 = p2 * p2, p8 = p4 * p4, p16 = p8 * p8;
#pragma unroll
                for (int n = 0; n < NST; n++) {
                    int m = n + 1;
                    float e = (m & 1) ? p1 : 1.f;
                    if (m & 2)  e *= p2;
                    if (m & 4)  e *= p4;
                    if (m & 8)  e *= p8;
                    if (m & 16) e *= p16;
                    hh[n] = e * hh[n] + du * sB[l * NST + n];
                }
            } else {
#pragma unroll
                for (int n = 0; n < NST; n++) {
                    float e = __expf(d * __ldg(&arow[n]));
                    hh[n] = e * hh[n] + du * sB[l * NST + n];
                }
            }
        }
        float* hrow = &sH[(size_t)(c * SPAT + dg) * 17];
#pragma unroll
        for (int n = 0; n < NST; n++) hrow[n] = hh[n];
        sS[c * 128 + dg] = S;
    }
    __syncthreads();

    // ---- Combine: prefix over chunk ends (done by chunk-0 lanes) ----
    if (act && c == 0) {
        for (int cc = 1; cc < NCHUNK - 1; cc++) {
            float Sc = sS[cc * 128 + dg];
            float* cur = &sH[(size_t)(cc * SPAT + dg) * 17];
            float* prv = &sH[(size_t)((cc - 1) * SPAT + dg) * 17];
            if (geo) {
                float p1 = __expf(Sc * a1);
                float p2 = p1 * p1, p4 = p2 * p2, p8 = p4 * p4, p16 = p8 * p8;
#pragma unroll
                for (int n = 0; n < NST; n++) {
                    int m = n + 1;
                    float e = (m & 1) ? p1 : 1.f;
                    if (m & 2)  e *= p2;
                    if (m & 4)  e *= p4;
                    if (m & 8)  e *= p8;
                    if (m & 16) e *= p16;
                    cur[n] += e * prv[n];
                }
            } else {
#pragma unroll
                for (int n = 0; n < NST; n++) {
                    float e = __expf(Sc * __ldg(&arow[n]));
                    cur[n] += e * prv[n];
                }
            }
        }
    }
    __syncthreads();

    // ---- Phase C: full scan seeded with true h0 ----
    if (act) {
        float hh[NST];
        if (c == 0) {
#pragma unroll
            for (int n = 0; n < NST; n++) hh[n] = 0.f;
        } else {
            const float* hrow = &sH[(size_t)((c - 1) * SPAT + dg) * 17];
#pragma unroll
            for (int n = 0; n < NST; n++) hh[n] = hrow[n];
        }
        float* yptr = ys + ((size_t)k * BL + (size_t)b * DI) * SPAT + dg;
        for (int l = l_beg; l < l_beg + LCHUNK; l++) {
            float dr = bias;
#pragma unroll
            for (int r = 0; r < RTK; r++) dr = fmaf(w8[r], sDT[l * RTK + r], dr);
            float d = softplus_f(dr);
            float uv = __ldg(&uptr[(size_t)l * SPAT]);
            float du = d * uv;
            float y = 0.f;
            if (geo) {
                float p1 = __expf(d * a1);
                float p2 = p1 * p1, p4 = p2 * p2, p8 = p4 * p4, p16 = p8 * p8;
#pragma unroll
                for (int n = 0; n < NST; n++) {
                    int m = n + 1;
                    float e = (m & 1) ? p1 : 1.f;
                    if (m & 2)  e *= p2;
                    if (m & 4)  e *= p4;
                    if (m & 8)  e *= p8;
                    if (m & 16) e *= p16;
                    hh[n] = e * hh[n] + du * sB[l * NST + n];
                    y += hh[n] * sC[l * NST + n];
                }
            } else {
#pragma unroll
                for (int n = 0; n < NST; n++) {
                    float e = __expf(d * __ldg(&arow[n]));
                    hh[n] = e * hh[n] + du * sB[l * NST + n];
                    y += hh[n] * sC[l * NST + n];
                }
            }
            yptr[(size_t)l * SPAT] = y + Dv * uv;
        }
    }
}

// ---------------- combine dirs + LayerNorm(dg) + gelu(z) gate; write [b][dg][l] ----------------
__global__ void __launch_bounds__(256) ln_kernel(
    const float* __restrict__ ys, const float* __restrict__ xz,
    const float* __restrict__ ln_g, const float* __restrict__ ln_b,
    float* __restrict__ ygT)
{
    __shared__ float tY[64 * 129];
    __shared__ float s_mu[64], s_rs[64];

    int lt = blockIdx.x;
    int b  = blockIdx.y;
    int t  = threadIdx.x;

    const float* ysA = ys + ((size_t)b * DI + lt * 64) * SPAT;
    const float* ysB = ys + (size_t)BL * SPAT + (size_t)b * DI * SPAT;

    for (int idx = t; idx < 64 * SPAT; idx += 256) {
        int l = idx / SPAT, dg = idx - l * SPAT;
        int gl = lt * 64 + l;
        float v = ysA[(size_t)l * SPAT + dg] + ysB[(size_t)(255 - gl) * SPAT + dg];
        tY[l * 129 + dg] = v;
    }
    __syncthreads();

    int w = t >> 5, lane = t & 31;
    for (int l = w * 8; l < w * 8 + 8; l++) {
        float s1 = 0.f, s2 = 0.f;
        for (int dg = lane; dg < SPAT; dg += 32) {
            float v = tY[l * 129 + dg];
            s1 += v; s2 += v * v;
        }
#pragma unroll
        for (int off = 16; off > 0; off >>= 1) {
            s1 += __shfl_xor_sync(0xffffffffu, s1, off);
            s2 += __shfl_xor_sync(0xffffffffu, s2, off);
        }
        if (lane == 0) {
            float mu = s1 * (1.f / SPAT);
            float var = s2 * (1.f / SPAT) - mu * mu;
            s_mu[l] = mu;
            s_rs[l] = rsqrtf(var + 1e-5f);
        }
    }
    __syncthreads();

    for (int idx = t; idx < SPAT * 64; idx += 256) {
        int dg = idx >> 6, l = idx & 63;
        int gl = lt * 64 + l;
        float v = (tY[l * 129 + dg] - s_mu[l]) * s_rs[l] * ln_g[dg] + ln_b[dg];
        float zv = xz[((size_t)b * SPAT + dg) * 512 + 256 + gl];
        float gz = 0.5f * zv * (1.f + erff(zv * 0.7071067811865475f));
        ygT[((size_t)b * SPAT + dg) * DI + gl] = v * gz;
    }
}

// ---------------- launcher ----------------
extern "C" void kernel_launch(void* const* d_in, const int* in_sizes, int n_in,
                              void* d_out, int out_size)
{
    const float* x         = (const float*)d_in[0];
    const float* in_proj_w = (const float*)d_in[1];
    const float* conv_w    = (const float*)d_in[2];
    const float* conv_b    = (const float*)d_in[3];
    const float* x_proj_w  = (const float*)d_in[4];
    const float* dt_proj_w = (const float*)d_in[5];
    const float* dt_proj_b = (const float*)d_in[6];
    const float* A_logs    = (const float*)d_in[7];
    const float* Ds        = (const float*)d_in[8];
    const float* ln_g      = (const float*)d_in[9];
    const float* ln_b      = (const float*)d_in[10];
    const float* out_proj_w= (const float*)d_in[11];
    float* out = (float*)d_out;

    float *p_xz, *p_u, *p_xdbl2, *p_ys, *p_ygT;
    cudaGetSymbolAddress((void**)&p_xz,    g_xz);
    cudaGetSymbolAddress((void**)&p_u,     g_u);
    cudaGetSymbolAddress((void**)&p_xdbl2, g_xdbl2);
    cudaGetSymbolAddress((void**)&p_ys,    g_ys);
    cudaGetSymbolAddress((void**)&p_ygT,   g_ygT);

    cudaFuncSetAttribute(scan_kernel,
                         cudaFuncAttributeMaxDynamicSharedMemorySize,
                         SCAN_SMEM_BYTES);

    // K1: xz = x @ in_proj_w.T   [15488,128] x [512,128]^T
    gemm128<<<dim3(ROWS / 128, 512 / 128), 256>>>(
        x, in_proj_w, p_xz, 512, DM, DM, DM, 512);

    // K2: depthwise conv + SiLU -> u[b][l][dg]
    conv_kernel<<<dim3(4, BATCH), 256>>>(p_xz, conv_w, conv_b, p_u);

    // K3: merged x_dbl for both dirs: [32768,121] x [80,121]^T -> [32768,80]
    gemm128<<<dim3(BL / 128, 1), 256>>>(
        p_u, x_proj_w, p_xdbl2, C80, SPAT, SPAT, SPAT, C80);

    // K4: chunk-parallel selective scan (dt-proj + softplus fused)
    scan_kernel<<<dim3(BATCH, 2), 512, SCAN_SMEM_BYTES>>>(
        p_xdbl2, p_u, dt_proj_w, dt_proj_b, A_logs, Ds, p_ys);

    // K5: combine directions + LN + gelu(z) gate -> ygT[b*121+dg][l]
    ln_kernel<<<dim3(4, BATCH), 256>>>(p_ys, p_xz, ln_g, ln_b, p_ygT);

    // K6: out = ygT @ out_proj_w.T   [15488,256] x [128,256]^T
    gemm128<<<dim3(ROWS / 128, 1), 256>>>(
        p_ygT, out_proj_w, out, DM, DI, DI, DI, DM);
}

// round 11
// speedup vs baseline: 2.3631x; 1.3975x over previous
#include <cuda_runtime.h>
#include <cuda_bf16.h>
#include <math.h>

// ---------------- problem constants ----------------
#define BATCH 128
#define SPAT  121          // H*W = d_spectral (dg)
#define DM    128          // d_model
#define DI    256          // d_inner = scan length L
#define NST   16           // d_state
#define RTK   8            // dt_rank
#define C40   40           // dt_rank + 2*NST per direction
#define C80   80           // merged both directions
#define ROWS  (BATCH*SPAT) // 15488
#define BL    (BATCH*DI)   // 32768 rows for per-(b,l) GEMMs

#define NCHUNK 4
#define LCHUNK (DI/NCHUNK) // 64

// dynamic smem layout for scan (floats)
#define SCAN_SMEM_FLOATS (18468 + 512)
#define SCAN_SMEM_BYTES  (SCAN_SMEM_FLOATS * 4)

// ---------------- scratch (device globals; no allocation allowed) ----------------
__device__ float g_xz   [ROWS*512];          // in_proj output [b*121+s][512]
__device__ float g_u    [BL*SPAT];           // conv+silu out, [b][l][dg]
__device__ float g_xdbl2[(size_t)BL*C80];    // merged x_dbl   [b*256+l][80]
__device__ float g_ys   [2ull*BL*SPAT];      // scan out       [k][b*256+l][dg]
__device__ float g_ygT  [ROWS*DI];           // LN*gelu(z)     [b*121+dg][l]

// ---------------- tf32 tensor-core GEMM ----------------
// C[r][c] = sum_k A[r][k] * W[c][k].  BM=128, BN=128, BK=32, 256 threads
// (8 warps in 4x2), warp tile 32x64 = 2x8 m16n8k8 fragments.
// VEC=1: float4 global loads (requires K%32==0, lda%4==0, ldb%4==0).
// VEC=0: scalar guarded loads (any K, any stride). M must be multiple of 128.

__device__ __forceinline__ unsigned f2tf32(float v) {
    unsigned r;
    asm("cvt.rna.tf32.f32 %0, %1;" : "=r"(r) : "f"(v));
    return r;
}

__device__ __forceinline__ void mma_tf32(float (&d)[4], const unsigned (&a)[4],
                                         const unsigned (&b)[2]) {
    asm volatile(
        "mma.sync.aligned.m16n8k8.row.col.f32.tf32.tf32.f32 "
        "{%0,%1,%2,%3}, {%4,%5,%6,%7}, {%8,%9}, {%0,%1,%2,%3};\n"
        : "+f"(d[0]), "+f"(d[1]), "+f"(d[2]), "+f"(d[3])
        : "r"(a[0]), "r"(a[1]), "r"(a[2]), "r"(a[3]), "r"(b[0]), "r"(b[1]));
}

#define SPAD 44   // smem row pad: (g*44+tig) % 32 conflict-free for fragment reads

template<int VEC>
__global__ void __launch_bounds__(256) gemm_tc(
    const float* __restrict__ A, const float* __restrict__ W,
    float* __restrict__ C, int N, int K, int lda, int ldb, int ldc)
{
    __shared__ unsigned As[128][SPAD];
    __shared__ unsigned Bs[128][SPAD];

    const int t    = threadIdx.x;
    const int wid  = t >> 5, lane = t & 31;
    const int g    = lane >> 2, tig = lane & 3;
    const int wm   = wid >> 1, wn = wid & 1;     // 4 x 2 warp grid
    const int rowBase = blockIdx.x * 128;
    const int colBase = blockIdx.y * 128;

    float acc[2][8][4];
#pragma unroll
    for (int mt = 0; mt < 2; mt++)
#pragma unroll
        for (int nt = 0; nt < 8; nt++)
#pragma unroll
            for (int q = 0; q < 4; q++) acc[mt][nt][q] = 0.f;

    for (int k0 = 0; k0 < K; k0 += 32) {
        // ---- load A,W tiles into smem (tf32-converted) ----
        if (VEC) {
#pragma unroll
            for (int j = 0; j < 4; j++) {
                int i  = t + j * 256;            // 0..1023 float4 slots
                int r  = i >> 3;
                int c4 = (i & 7) << 2;
                float4 va = *(const float4*)&A[(size_t)(rowBase + r) * lda + k0 + c4];
                As[r][c4 + 0] = f2tf32(va.x);
                As[r][c4 + 1] = f2tf32(va.y);
                As[r][c4 + 2] = f2tf32(va.z);
                As[r][c4 + 3] = f2tf32(va.w);
                float4 vb;
                if (colBase + r < N)
                    vb = *(const float4*)&W[(size_t)(colBase + r) * ldb + k0 + c4];
                else
                    vb = make_float4(0.f, 0.f, 0.f, 0.f);
                Bs[r][c4 + 0] = f2tf32(vb.x);
                Bs[r][c4 + 1] = f2tf32(vb.y);
                Bs[r][c4 + 2] = f2tf32(vb.z);
                Bs[r][c4 + 3] = f2tf32(vb.w);
            }
        } else {
#pragma unroll
            for (int j = 0; j < 16; j++) {
                int i  = t + j * 256;            // 0..4095 scalar slots
                int r  = i >> 5;
                int kk = i & 31;
                int gk = k0 + kk;
                float va = (gk < K) ? A[(size_t)(rowBase + r) * lda + gk] : 0.f;
                As[r][kk] = f2tf32(va);
                float vb = (gk < K && colBase + r < N)
                           ? W[(size_t)(colBase + r) * ldb + gk] : 0.f;
                Bs[r][kk] = f2tf32(vb);
            }
        }
        __syncthreads();

        // ---- 4 k-steps of m16n8k8 ----
#pragma unroll
        for (int ks = 0; ks < 4; ks++) {
            const int kk = ks * 8;
            unsigned af[2][4], bf[8][2];
#pragma unroll
            for (int mt = 0; mt < 2; mt++) {
                int row = wm * 32 + mt * 16 + g;
                af[mt][0] = As[row    ][kk + tig];
                af[mt][1] = As[row + 8][kk + tig];
                af[mt][2] = As[row    ][kk + tig + 4];
                af[mt][3] = As[row + 8][kk + tig + 4];
            }
#pragma unroll
            for (int nt = 0; nt < 8; nt++) {
                int col = wn * 64 + nt * 8 + g;
                bf[nt][0] = Bs[col][kk + tig];
                bf[nt][1] = Bs[col][kk + tig + 4];
            }
#pragma unroll
            for (int mt = 0; mt < 2; mt++)
#pragma unroll
                for (int nt = 0; nt < 8; nt++)
                    mma_tf32(acc[mt][nt], af[mt], bf[nt]);
        }
        __syncthreads();
    }

    // ---- writeback ----
#pragma unroll
    for (int mt = 0; mt < 2; mt++) {
#pragma unroll
        for (int nt = 0; nt < 8; nt++) {
            int row0 = rowBase + wm * 32 + mt * 16 + g;
            int col0 = colBase + wn * 64 + nt * 8 + 2 * tig;
            if (col0 < N) {
                C[(size_t)row0 * ldc + col0]           = acc[mt][nt][0];
                C[(size_t)(row0 + 8) * ldc + col0]     = acc[mt][nt][2];
            }
            if (col0 + 1 < N) {
                C[(size_t)row0 * ldc + col0 + 1]       = acc[mt][nt][1];
                C[(size_t)(row0 + 8) * ldc + col0 + 1] = acc[mt][nt][3];
            }
        }
    }
}

// ---------------- depthwise 3x3 conv + SiLU, xz[:, :256] -> u[b][l][dg] ----------------
__global__ void __launch_bounds__(256) conv_kernel(
    const float* __restrict__ xz, const float* __restrict__ conv_w,
    const float* __restrict__ conv_b, float* __restrict__ u)
{
    __shared__ float s_in[SPAT * 65];
    int ct = blockIdx.x;
    int b  = blockIdx.y;
    int t  = threadIdx.x;

    for (int idx = t; idx < SPAT * 64; idx += 256) {
        int s = idx >> 6, c = idx & 63;
        s_in[s * 65 + c] = xz[((size_t)b * SPAT + s) * 512 + ct * 64 + c];
    }
    __syncthreads();

    size_t base = ((size_t)b * DI + ct * 64) * SPAT;
    for (int idx = t; idx < 64 * SPAT; idx += 256) {
        int c = idx / SPAT;
        int s = idx - c * SPAT;
        int i = s / 11, j = s - i * 11;
        int ch = ct * 64 + c;
        float acc = conv_b[ch];
#pragma unroll
        for (int ti = 0; ti < 3; ti++) {
            int ii = i + ti - 1;
            if ((unsigned)ii < 11u) {
#pragma unroll
                for (int tj = 0; tj < 3; tj++) {
                    int jj = j + tj - 1;
                    if ((unsigned)jj < 11u)
                        acc += s_in[(ii * 11 + jj) * 65 + c] * conv_w[ch * 9 + ti * 3 + tj];
                }
            }
        }
        float sv = acc / (1.f + __expf(-acc));
        u[base + idx] = sv;
    }
}

// ---------------- chunk-parallel selective scan ----------------
__device__ __forceinline__ float softplus_f(float x) {
    return (x > 20.f) ? x : log1pf(__expf(x));
}

__global__ void __launch_bounds__(512, 2) scan_kernel(
    const float* __restrict__ xdbl2, const float* __restrict__ u,
    const float* __restrict__ dt_proj_w, const float* __restrict__ dt_proj_b,
    const float* __restrict__ A_logs, const float* __restrict__ Ds,
    float* __restrict__ ys)
{
    extern __shared__ float sm[];
    float* sDT = sm;            // [l*8+r]
    float* sB  = sm + 2048;     // [l*16+n]
    float* sC  = sm + 6144;     // [l*16+n]
    float* sH  = sm + 10240;    // [(c*121+dg)*17+n]
    float* sS  = sm + 18468;    // [c*128+dg]

    const int b   = blockIdx.x;
    const int k   = blockIdx.y;
    const int tid = threadIdx.x;
    const int c   = tid >> 7;
    const int dg  = tid & 127;
    const bool act = dg < SPAT;

    const float* xd = xdbl2 + ((size_t)b * DI) * C80 + k * C40;
    for (int idx = tid; idx < DI * C40; idx += 512) {
        int l = idx / C40, cc = idx - l * C40;
        float v = __ldg(&xd[(size_t)l * C80 + cc]);
        if (cc < RTK)            sDT[l * RTK + cc] = v;
        else if (cc < RTK + NST) sB[l * NST + (cc - RTK)] = v;
        else                     sC[l * NST + (cc - RTK - NST)] = v;
    }

    float w8[RTK];
    float a1 = 0.f, bias = 0.f, Dv = 0.f;
    bool geo = false;
    const float* arow = A_logs + ((size_t)k * SPAT + (act ? dg : 0)) * NST;
    if (act) {
        a1 = -expf(arow[0]);
        geo = true;
#pragma unroll
        for (int n = 0; n < NST; n++) {
            float an = -expf(arow[n]);
            float tgt = (float)(n + 1) * a1;
            if (fabsf(an - tgt) > 1e-5f * (float)(n + 1) * fabsf(a1)) geo = false;
        }
        Dv = Ds[k * SPAT + dg];
        const float* wrow = dt_proj_w + ((size_t)k * SPAT + dg) * RTK;
#pragma unroll
        for (int r = 0; r < RTK; r++) w8[r] = wrow[r];
        bias = dt_proj_b[k * SPAT + dg];
    }
    __syncthreads();

    const float* uptr = u + ((size_t)b * DI) * SPAT + dg;
    const int l_beg = c * LCHUNK;

    // ---- Phase A: local scan, chunks 0..2 ----
    if (act && c < NCHUNK - 1) {
        float hh[NST];
#pragma unroll
        for (int n = 0; n < NST; n++) hh[n] = 0.f;
        float S = 0.f;
        for (int l = l_beg; l < l_beg + LCHUNK; l++) {
            float dr = bias;
#pragma unroll
            for (int r = 0; r < RTK; r++) dr = fmaf(w8[r], sDT[l * RTK + r], dr);
            float d = softplus_f(dr);
            S += d;
            float du = d * __ldg(&uptr[(size_t)l * SPAT]);
            if (geo) {
                float p1 = __expf(d * a1);
                float p2 = p1 * p1, p4 = p2 * p2, p8 = p4 * p4, p16 = p8 * p8;
#pragma unroll
                for (int n = 0; n < NST; n++) {
                    int m = n + 1;
                    float e = (m & 1) ? p1 : 1.f;
                    if (m & 2)  e *= p2;
                    if (m & 4)  e *= p4;
                    if (m & 8)  e *= p8;
                    if (m & 16) e *= p16;
                    hh[n] = e * hh[n] + du * sB[l * NST + n];
                }
            } else {
#pragma unroll
                for (int n = 0; n < NST; n++) {
                    float e = __expf(d * __ldg(&arow[n]));
                    hh[n] = e * hh[n] + du * sB[l * NST + n];
                }
            }
        }
        float* hrow = &sH[(size_t)(c * SPAT + dg) * 17];
#pragma unroll
        for (int n = 0; n < NST; n++) hrow[n] = hh[n];
        sS[c * 128 + dg] = S;
    }
    __syncthreads();

    // ---- Combine: prefix over chunk ends ----
    if (act && c == 0) {
        for (int cc = 1; cc < NCHUNK - 1; cc++) {
            float Sc = sS[cc * 128 + dg];
            float* cur = &sH[(size_t)(cc * SPAT + dg) * 17];
            float* prv = &sH[(size_t)((cc - 1) * SPAT + dg) * 17];
            if (geo) {
                float p1 = __expf(Sc * a1);
                float p2 = p1 * p1, p4 = p2 * p2, p8 = p4 * p4, p16 = p8 * p8;
#pragma unroll
                for (int n = 0; n < NST; n++) {
                    int m = n + 1;
                    float e = (m & 1) ? p1 : 1.f;
                    if (m & 2)  e *= p2;
                    if (m & 4)  e *= p4;
                    if (m & 8)  e *= p8;
                    if (m & 16) e *= p16;
                    cur[n] += e * prv[n];
                }
            } else {
#pragma unroll
                for (int n = 0; n < NST; n++) {
                    float e = __expf(Sc * __ldg(&arow[n]));
                    cur[n] += e * prv[n];
                }
            }
        }
    }
    __syncthreads();

    // ---- Phase C: full scan seeded with true h0 ----
    if (act) {
        float hh[NST];
        if (c == 0) {
#pragma unroll
            for (int n = 0; n < NST; n++) hh[n] = 0.f;
        } else {
            const float* hrow = &sH[(size_t)((c - 1) * SPAT + dg) * 17];
#pragma unroll
            for (int n = 0; n < NST; n++) hh[n] = hrow[n];
        }
        float* yptr = ys + ((size_t)k * BL + (size_t)b * DI) * SPAT + dg;
        for (int l = l_beg; l < l_beg + LCHUNK; l++) {
            float dr = bias;
#pragma unroll
            for (int r = 0; r < RTK; r++) dr = fmaf(w8[r], sDT[l * RTK + r], dr);
            float d = softplus_f(dr);
            float uv = __ldg(&uptr[(size_t)l * SPAT]);
            float du = d * uv;
            float y = 0.f;
            if (geo) {
                float p1 = __expf(d * a1);
                float p2 = p1 * p1, p4 = p2 * p2, p8 = p4 * p4, p16 = p8 * p8;
#pragma unroll
                for (int n = 0; n < NST; n++) {
                    int m = n + 1;
                    float e = (m & 1) ? p1 : 1.f;
                    if (m & 2)  e *= p2;
                    if (m & 4)  e *= p4;
                    if (m & 8)  e *= p8;
                    if (m & 16) e *= p16;
                    hh[n] = e * hh[n] + du * sB[l * NST + n];
                    y += hh[n] * sC[l * NST + n];
                }
            } else {
#pragma unroll
                for (int n = 0; n < NST; n++) {
                    float e = __expf(d * __ldg(&arow[n]));
                    hh[n] = e * hh[n] + du * sB[l * NST + n];
                    y += hh[n] * sC[l * NST + n];
                }
            }
            yptr[(size_t)l * SPAT] = y + Dv * uv;
        }
    }
}

// ---------------- combine dirs + LayerNorm(dg) + gelu(z) gate; write [b][dg][l] ----------------
__global__ void __launch_bounds__(256) ln_kernel(
    const float* __restrict__ ys, const float* __restrict__ xz,
    const float* __restrict__ ln_g, const float* __restrict__ ln_b,
    float* __restrict__ ygT)
{
    __shared__ float tY[64 * 129];
    __shared__ float s_mu[64], s_rs[64];

    int lt = blockIdx.x;
    int b  = blockIdx.y;
    int t  = threadIdx.x;

    const float* ysA = ys + ((size_t)b * DI + lt * 64) * SPAT;
    const float* ysB = ys + (size_t)BL * SPAT + (size_t)b * DI * SPAT;

    for (int idx = t; idx < 64 * SPAT; idx += 256) {
        int l = idx / SPAT, dg = idx - l * SPAT;
        int gl = lt * 64 + l;
        float v = ysA[(size_t)l * SPAT + dg] + ysB[(size_t)(255 - gl) * SPAT + dg];
        tY[l * 129 + dg] = v;
    }
    __syncthreads();

    int w = t >> 5, lane = t & 31;
    for (int l = w * 8; l < w * 8 + 8; l++) {
        float s1 = 0.f, s2 = 0.f;
        for (int dg = lane; dg < SPAT; dg += 32) {
            float v = tY[l * 129 + dg];
            s1 += v; s2 += v * v;
        }
#pragma unroll
        for (int off = 16; off > 0; off >>= 1) {
            s1 += __shfl_xor_sync(0xffffffffu, s1, off);
            s2 += __shfl_xor_sync(0xffffffffu, s2, off);
        }
        if (lane == 0) {
            float mu = s1 * (1.f / SPAT);
            float var = s2 * (1.f / SPAT) - mu * mu;
            s_mu[l] = mu;
            s_rs[l] = rsqrtf(var + 1e-5f);
        }
    }
    __syncthreads();

    for (int idx = t; idx < SPAT * 64; idx += 256) {
        int dg = idx >> 6, l = idx & 63;
        int gl = lt * 64 + l;
        float v = (tY[l * 129 + dg] - s_mu[l]) * s_rs[l] * ln_g[dg] + ln_b[dg];
        float zv = xz[((size_t)b * SPAT + dg) * 512 + 256 + gl];
        float gz = 0.5f * zv * (1.f + erff(zv * 0.7071067811865475f));
        ygT[((size_t)b * SPAT + dg) * DI + gl] = v * gz;
    }
}

// ---------------- launcher ----------------
extern "C" void kernel_launch(void* const* d_in, const int* in_sizes, int n_in,
                              void* d_out, int out_size)
{
    const float* x         = (const float*)d_in[0];
    const float* in_proj_w = (const float*)d_in[1];
    const float* conv_w    = (const float*)d_in[2];
    const float* conv_b    = (const float*)d_in[3];
    const float* x_proj_w  = (const float*)d_in[4];
    const float* dt_proj_w = (const float*)d_in[5];
    const float* dt_proj_b = (const float*)d_in[6];
    const float* A_logs    = (const float*)d_in[7];
    const float* Ds        = (const float*)d_in[8];
    const float* ln_g      = (const float*)d_in[9];
    const float* ln_b      = (const float*)d_in[10];
    const float* out_proj_w= (const float*)d_in[11];
    float* out = (float*)d_out;

    float *p_xz, *p_u, *p_xdbl2, *p_ys, *p_ygT;
    cudaGetSymbolAddress((void**)&p_xz,    g_xz);
    cudaGetSymbolAddress((void**)&p_u,     g_u);
    cudaGetSymbolAddress((void**)&p_xdbl2, g_xdbl2);
    cudaGetSymbolAddress((void**)&p_ys,    g_ys);
    cudaGetSymbolAddress((void**)&p_ygT,   g_ygT);

    cudaFuncSetAttribute(scan_kernel,
                         cudaFuncAttributeMaxDynamicSharedMemorySize,
                         SCAN_SMEM_BYTES);

    // K1: xz = x @ in_proj_w.T   [15488,128] x [512,128]^T  (K=128: vec path)
    gemm_tc<1><<<dim3(ROWS / 128, 4), 256>>>(
        x, in_proj_w, p_xz, 512, DM, DM, DM, 512);

    // K2: depthwise conv + SiLU -> u[b][l][dg]
    conv_kernel<<<dim3(4, BATCH), 256>>>(p_xz, conv_w, conv_b, p_u);

    // K3: merged x_dbl: [32768,121] x [80,121]^T -> [32768,80]  (K=121: scalar path)
    gemm_tc<0><<<dim3(BL / 128, 1), 256>>>(
        p_u, x_proj_w, p_xdbl2, C80, SPAT, SPAT, SPAT, C80);

    // K4: chunk-parallel selective scan (dt-proj + softplus fused)
    scan_kernel<<<dim3(BATCH, 2), 512, SCAN_SMEM_BYTES>>>(
        p_xdbl2, p_u, dt_proj_w, dt_proj_b, A_logs, Ds, p_ys);

    // K5: combine directions + LN + gelu(z) gate -> ygT[b*121+dg][l]
    ln_kernel<<<dim3(4, BATCH), 256>>>(p_ys, p_xz, ln_g, ln_b, p_ygT);

    // K6: out = ygT @ out_proj_w.T   [15488,256] x [128,256]^T  (K=256: vec path)
    gemm_tc<1><<<dim3(ROWS / 128, 1), 256>>>(
        p_ygT, out_proj_w, out, DM, DI, DI, DI, DM);
}

// round 12
// speedup vs baseline: 2.5116x; 1.0628x over previous
#include <cuda_runtime.h>
#include <cuda_bf16.h>
#include <math.h>

// ---------------- problem constants ----------------
#define BATCH 128
#define SPAT  121          // H*W = d_spectral (dg)
#define DM    128          // d_model
#define DI    256          // d_inner = scan length L
#define NST   16           // d_state
#define RTK   8            // dt_rank
#define C40   40           // dt_rank + 2*NST per direction
#define C80   80           // merged both directions
#define ROWS  (BATCH*SPAT) // 15488
#define BL    (BATCH*DI)   // 32768 rows for per-(b,l) GEMMs

#define NCHUNK 4
#define LCHUNK (DI/NCHUNK) // 64

// scan dynamic smem (floats): sB@0[4096] sC@4096[4096] sH@8192[4*121*18=8712] sS@16904[512]
#define SH_B  0
#define SH_C  4096
#define SH_H  8192
#define SH_S  16904
#define SCAN_SMEM_FLOATS (SH_S + 512)
#define SCAN_SMEM_BYTES  (SCAN_SMEM_FLOATS * 4)

// ---------------- scratch (device globals; no allocation allowed) ----------------
__device__ float g_xz   [ROWS*512];          // in_proj output [b*121+s][512]
__device__ float g_u    [BL*SPAT];           // conv+silu out, [b][l][dg]
__device__ float g_xdbl2[(size_t)BL*C80];    // merged x_dbl   [b*256+l][80]
__device__ float g_delta[2ull*BL*SPAT];      // softplus dt    [k][b*256+l][dg]
__device__ float g_ys   [2ull*BL*SPAT];      // scan out       [k][b*256+l][dg]
__device__ float g_ygT  [ROWS*DI];           // LN*gelu(z)     [b*121+dg][l]

// ---------------- packed f32x2 helpers (Blackwell FFMA2 path) ----------------
typedef unsigned long long ull;
__device__ __forceinline__ ull pk2(float lo, float hi) {
    ull r; asm("mov.b64 %0, {%1, %2};" : "=l"(r) : "f"(lo), "f"(hi)); return r;
}
__device__ __forceinline__ float2 upk2(ull v) {
    float2 f; asm("mov.b64 {%0, %1}, %2;" : "=f"(f.x), "=f"(f.y) : "l"(v)); return f;
}
__device__ __forceinline__ ull fma2(ull a, ull b, ull c) {
    ull d; asm("fma.rn.f32x2 %0, %1, %2, %3;" : "=l"(d) : "l"(a), "l"(b), "l"(c)); return d;
}
__device__ __forceinline__ ull mul2(ull a, ull b) {
    ull d; asm("mul.rn.f32x2 %0, %1, %2;" : "=l"(d) : "l"(a), "l"(b)); return d;
}

// ---------------- tf32 tensor-core GEMM ----------------
__device__ __forceinline__ unsigned f2tf32(float v) {
    unsigned r;
    asm("cvt.rna.tf32.f32 %0, %1;" : "=r"(r) : "f"(v));
    return r;
}

__device__ __forceinline__ void mma_tf32(float (&d)[4], const unsigned (&a)[4],
                                         const unsigned (&b)[2]) {
    asm volatile(
        "mma.sync.aligned.m16n8k8.row.col.f32.tf32.tf32.f32 "
        "{%0,%1,%2,%3}, {%4,%5,%6,%7}, {%8,%9}, {%0,%1,%2,%3};\n"
        : "+f"(d[0]), "+f"(d[1]), "+f"(d[2]), "+f"(d[3])
        : "r"(a[0]), "r"(a[1]), "r"(a[2]), "r"(a[3]), "r"(b[0]), "r"(b[1]));
}

#define SPAD 44

template<int VEC>
__global__ void __launch_bounds__(256) gemm_tc(
    const float* __restrict__ A, const float* __restrict__ W,
    float* __restrict__ C, int N, int K, int lda, int ldb, int ldc)
{
    __shared__ unsigned As[128][SPAD];
    __shared__ unsigned Bs[128][SPAD];

    const int t    = threadIdx.x;
    const int wid  = t >> 5, lane = t & 31;
    const int g    = lane >> 2, tig = lane & 3;
    const int wm   = wid >> 1, wn = wid & 1;
    const int rowBase = blockIdx.x * 128;
    const int colBase = blockIdx.y * 128;

    float acc[2][8][4];
#pragma unroll
    for (int mt = 0; mt < 2; mt++)
#pragma unroll
        for (int nt = 0; nt < 8; nt++)
#pragma unroll
            for (int q = 0; q < 4; q++) acc[mt][nt][q] = 0.f;

    for (int k0 = 0; k0 < K; k0 += 32) {
        if (VEC) {
#pragma unroll
            for (int j = 0; j < 4; j++) {
                int i  = t + j * 256;
                int r  = i >> 3;
                int c4 = (i & 7) << 2;
                float4 va = *(const float4*)&A[(size_t)(rowBase + r) * lda + k0 + c4];
                As[r][c4 + 0] = f2tf32(va.x);
                As[r][c4 + 1] = f2tf32(va.y);
                As[r][c4 + 2] = f2tf32(va.z);
                As[r][c4 + 3] = f2tf32(va.w);
                float4 vb;
                if (colBase + r < N)
                    vb = *(const float4*)&W[(size_t)(colBase + r) * ldb + k0 + c4];
                else
                    vb = make_float4(0.f, 0.f, 0.f, 0.f);
                Bs[r][c4 + 0] = f2tf32(vb.x);
                Bs[r][c4 + 1] = f2tf32(vb.y);
                Bs[r][c4 + 2] = f2tf32(vb.z);
                Bs[r][c4 + 3] = f2tf32(vb.w);
            }
        } else {
#pragma unroll
            for (int j = 0; j < 16; j++) {
                int i  = t + j * 256;
                int r  = i >> 5;
                int kk = i & 31;
                int gk = k0 + kk;
                float va = (gk < K) ? A[(size_t)(rowBase + r) * lda + gk] : 0.f;
                As[r][kk] = f2tf32(va);
                float vb = (gk < K && colBase + r < N)
                           ? W[(size_t)(colBase + r) * ldb + gk] : 0.f;
                Bs[r][kk] = f2tf32(vb);
            }
        }
        __syncthreads();

#pragma unroll
        for (int ks = 0; ks < 4; ks++) {
            const int kk = ks * 8;
            unsigned af[2][4], bf[8][2];
#pragma unroll
            for (int mt = 0; mt < 2; mt++) {
                int row = wm * 32 + mt * 16 + g;
                af[mt][0] = As[row    ][kk + tig];
                af[mt][1] = As[row + 8][kk + tig];
                af[mt][2] = As[row    ][kk + tig + 4];
                af[mt][3] = As[row + 8][kk + tig + 4];
            }
#pragma unroll
            for (int nt = 0; nt < 8; nt++) {
                int col = wn * 64 + nt * 8 + g;
                bf[nt][0] = Bs[col][kk + tig];
                bf[nt][1] = Bs[col][kk + tig + 4];
            }
#pragma unroll
            for (int mt = 0; mt < 2; mt++)
#pragma unroll
                for (int nt = 0; nt < 8; nt++)
                    mma_tf32(acc[mt][nt], af[mt], bf[nt]);
        }
        __syncthreads();
    }

#pragma unroll
    for (int mt = 0; mt < 2; mt++) {
#pragma unroll
        for (int nt = 0; nt < 8; nt++) {
            int row0 = rowBase + wm * 32 + mt * 16 + g;
            int col0 = colBase + wn * 64 + nt * 8 + 2 * tig;
            if (col0 < N) {
                C[(size_t)row0 * ldc + col0]           = acc[mt][nt][0];
                C[(size_t)(row0 + 8) * ldc + col0]     = acc[mt][nt][2];
            }
            if (col0 + 1 < N) {
                C[(size_t)row0 * ldc + col0 + 1]       = acc[mt][nt][1];
                C[(size_t)(row0 + 8) * ldc + col0 + 1] = acc[mt][nt][3];
            }
        }
    }
}

// ---------------- depthwise 3x3 conv + SiLU, xz[:, :256] -> u[b][l][dg] ----------------
__global__ void __launch_bounds__(256) conv_kernel(
    const float* __restrict__ xz, const float* __restrict__ conv_w,
    const float* __restrict__ conv_b, float* __restrict__ u)
{
    __shared__ float s_in[SPAT * 65];
    int ct = blockIdx.x;
    int b  = blockIdx.y;
    int t  = threadIdx.x;

    for (int idx = t; idx < SPAT * 64; idx += 256) {
        int s = idx >> 6, c = idx & 63;
        s_in[s * 65 + c] = xz[((size_t)b * SPAT + s) * 512 + ct * 64 + c];
    }
    __syncthreads();

    size_t base = ((size_t)b * DI + ct * 64) * SPAT;
    for (int idx = t; idx < 64 * SPAT; idx += 256) {
        int c = idx / SPAT;
        int s = idx - c * SPAT;
        int i = s / 11, j = s - i * 11;
        int ch = ct * 64 + c;
        float acc = conv_b[ch];
#pragma unroll
        for (int ti = 0; ti < 3; ti++) {
            int ii = i + ti - 1;
            if ((unsigned)ii < 11u) {
#pragma unroll
                for (int tj = 0; tj < 3; tj++) {
                    int jj = j + tj - 1;
                    if ((unsigned)jj < 11u)
                        acc += s_in[(ii * 11 + jj) * 65 + c] * conv_w[ch * 9 + ti * 3 + tj];
                }
            }
        }
        float sv = acc / (1.f + __expf(-acc));
        u[base + idx] = sv;
    }
}

// ---------------- delta precompute: softplus(dts @ dt_proj_w^T + b) ----------------
// grid (BATCH, 2), 512 threads: lgrp = tid>>7 (l stride 4), dg = tid&127.
__global__ void __launch_bounds__(512) delta_kernel(
    const float* __restrict__ xdbl2, const float* __restrict__ dt_proj_w,
    const float* __restrict__ dt_proj_b, float* __restrict__ delta)
{
    __shared__ float sdt[DI][RTK];   // 8 KB

    const int b = blockIdx.x;
    const int k = blockIdx.y;
    const int tid = threadIdx.x;
    const int lgrp = tid >> 7;
    const int dg = tid & 127;
    const bool act = dg < SPAT;

    const float* xd = xdbl2 + ((size_t)b * DI) * C80 + k * C40;
    for (int idx = tid; idx < DI * RTK; idx += 512) {
        int l = idx >> 3, r = idx & 7;
        sdt[l][r] = __ldg(&xd[(size_t)l * C80 + r]);
    }

    float w8[RTK];
    float bias = 0.f;
    if (act) {
        const float* wrow = dt_proj_w + ((size_t)k * SPAT + dg) * RTK;
#pragma unroll
        for (int r = 0; r < RTK; r++) w8[r] = wrow[r];
        bias = dt_proj_b[k * SPAT + dg];
    }
    __syncthreads();

    if (!act) return;
    float* dout = delta + ((size_t)k * BL + (size_t)b * DI) * SPAT + dg;
    for (int l = lgrp; l < DI; l += 4) {
        float dr = bias;
#pragma unroll
        for (int r = 0; r < RTK; r++) dr = fmaf(w8[r], sdt[l][r], dr);
        dout[(size_t)l * SPAT] = (dr > 20.f) ? dr : log1pf(__expf(dr));
    }
}

// ---------------- chunk-parallel selective scan (packed f32x2 hot loop) ----------------
__global__ void __launch_bounds__(512, 2) scan_kernel(
    const float* __restrict__ xdbl2, const float* __restrict__ u,
    const float* __restrict__ delta,
    const float* __restrict__ A_logs, const float* __restrict__ Ds,
    float* __restrict__ ys)
{
    extern __shared__ float sm[];
    float* sB = sm + SH_B;      // [l*16+n]
    float* sC = sm + SH_C;      // [l*16+n]
    float* sH = sm + SH_H;      // [(c*121+dg)*18+n]
    float* sS = sm + SH_S;      // [c*128+dg]

    const int b   = blockIdx.x;
    const int k   = blockIdx.y;
    const int tid = threadIdx.x;
    const int c   = tid >> 7;
    const int dg  = tid & 127;
    const bool act = dg < SPAT;

    // stage B,C (cols 8..39 of this dir's 40-wide slice)
    const float* xd = xdbl2 + ((size_t)b * DI) * C80 + k * C40 + RTK;
    for (int idx = tid; idx < DI * 32; idx += 512) {
        int l = idx >> 5, cc = idx & 31;
        float v = __ldg(&xd[(size_t)l * C80 + cc]);
        if (cc < NST) sB[l * NST + cc] = v;
        else          sC[l * NST + (cc - NST)] = v;
    }

    float a1 = 0.f, Dv = 0.f;
    bool geo = false;
    const float* arow = A_logs + ((size_t)k * SPAT + (act ? dg : 0)) * NST;
    if (act) {
        a1 = -expf(arow[0]);
        geo = true;
#pragma unroll
        for (int n = 0; n < NST; n++) {
            float an = -expf(arow[n]);
            float tgt = (float)(n + 1) * a1;
            if (fabsf(an - tgt) > 1e-5f * (float)(n + 1) * fabsf(a1)) geo = false;
        }
        Dv = Ds[k * SPAT + dg];
    }
    __syncthreads();

    const float* uptr = u     + ((size_t)b * DI) * SPAT + dg;
    const float* dptr = delta + ((size_t)k * BL + (size_t)b * DI) * SPAT + dg;
    const int l_beg = c * LCHUNK;

    // ---- Phase A: local scan, chunks 0..2 ----
    if (act && c < NCHUNK - 1) {
        ull hh2[8];
#pragma unroll
        for (int j = 0; j < 8; j++) hh2[j] = pk2(0.f, 0.f);
        float S = 0.f;
        if (geo) {
#pragma unroll 2
            for (int l = l_beg; l < l_beg + LCHUNK; l++) {
                float d  = dptr[(size_t)l * SPAT];
                float uv = uptr[(size_t)l * SPAT];
                S += d;
                float du = d * uv;
                float q1 = __expf(d * a1);
                float q2 = q1 * q1;
                ull e2 = pk2(q1, q2), qq = pk2(q2, q2), du2 = pk2(du, du);
                const float4* B4 = (const float4*)&sB[l * NST];
#pragma unroll
                for (int jj = 0; jj < 4; jj++) {
                    float4 bb = B4[jj];
                    hh2[2*jj]   = fma2(e2, hh2[2*jj],   mul2(du2, pk2(bb.x, bb.y)));
                    e2 = mul2(e2, qq);
                    hh2[2*jj+1] = fma2(e2, hh2[2*jj+1], mul2(du2, pk2(bb.z, bb.w)));
                    e2 = mul2(e2, qq);
                }
            }
        } else {
            float hs[NST];
#pragma unroll
            for (int n = 0; n < NST; n++) hs[n] = 0.f;
            for (int l = l_beg; l < l_beg + LCHUNK; l++) {
                float d  = dptr[(size_t)l * SPAT];
                float uv = uptr[(size_t)l * SPAT];
                S += d;
                float du = d * uv;
#pragma unroll
                for (int n = 0; n < NST; n++) {
                    float e = __expf(d * __ldg(&arow[n]));
                    hs[n] = e * hs[n] + du * sB[l * NST + n];
                }
            }
#pragma unroll
            for (int j = 0; j < 8; j++) hh2[j] = pk2(hs[2*j], hs[2*j+1]);
        }
        float* hrow = &sH[(size_t)(c * SPAT + dg) * 18];
#pragma unroll
        for (int j = 0; j < 8; j++) {
            float2 hv = upk2(hh2[j]);
            hrow[2*j] = hv.x; hrow[2*j+1] = hv.y;
        }
        sS[c * 128 + dg] = S;
    }
    __syncthreads();

    // ---- Combine: prefix over chunk ends ----
    if (act && c == 0) {
        for (int cc = 1; cc < NCHUNK - 1; cc++) {
            float Sc = sS[cc * 128 + dg];
            float* cur = &sH[(size_t)(cc * SPAT + dg) * 18];
            float* prv = &sH[(size_t)((cc - 1) * SPAT + dg) * 18];
            if (geo) {
                float p1 = __expf(Sc * a1);
                float e = 1.f;
#pragma unroll
                for (int n = 0; n < NST; n++) {
                    e *= p1;
                    cur[n] += e * prv[n];
                }
            } else {
#pragma unroll
                for (int n = 0; n < NST; n++) {
                    float e = __expf(Sc * __ldg(&arow[n]));
                    cur[n] += e * prv[n];
                }
            }
        }
    }
    __syncthreads();

    // ---- Phase C: full scan seeded with true h0 ----
    if (act) {
        ull hh2[8];
        if (c == 0) {
#pragma unroll
            for (int j = 0; j < 8; j++) hh2[j] = pk2(0.f, 0.f);
        } else {
            const float* hrow = &sH[(size_t)((c - 1) * SPAT + dg) * 18];
#pragma unroll
            for (int j = 0; j < 8; j++) hh2[j] = pk2(hrow[2*j], hrow[2*j+1]);
        }
        float* yptr = ys + ((size_t)k * BL + (size_t)b * DI) * SPAT + dg;
        if (geo) {
#pragma unroll 2
            for (int l = l_beg; l < l_beg + LCHUNK; l++) {
                float d  = dptr[(size_t)l * SPAT];
                float uv = uptr[(size_t)l * SPAT];
                float du = d * uv;
                float q1 = __expf(d * a1);
                float q2 = q1 * q1;
                ull e2 = pk2(q1, q2), qq = pk2(q2, q2), du2 = pk2(du, du);
                ull yacc = pk2(0.f, 0.f);
                const float4* B4 = (const float4*)&sB[l * NST];
                const float4* C4 = (const float4*)&sC[l * NST];
#pragma unroll
                for (int jj = 0; jj < 4; jj++) {
                    float4 bb = B4[jj];
                    float4 cv = C4[jj];
                    hh2[2*jj]   = fma2(e2, hh2[2*jj],   mul2(du2, pk2(bb.x, bb.y)));
                    yacc        = fma2(hh2[2*jj], pk2(cv.x, cv.y), yacc);
                    e2 = mul2(e2, qq);
                    hh2[2*jj+1] = fma2(e2, hh2[2*jj+1], mul2(du2, pk2(bb.z, bb.w)));
                    yacc        = fma2(hh2[2*jj+1], pk2(cv.z, cv.w), yacc);
                    e2 = mul2(e2, qq);
                }
                float2 yv = upk2(yacc);
                yptr[(size_t)l * SPAT] = yv.x + yv.y + Dv * uv;
            }
        } else {
            float hs[NST];
#pragma unroll
            for (int j = 0; j < 8; j++) {
                float2 hv = upk2(hh2[j]);
                hs[2*j] = hv.x; hs[2*j+1] = hv.y;
            }
            for (int l = l_beg; l < l_beg + LCHUNK; l++) {
                float d  = dptr[(size_t)l * SPAT];
                float uv = uptr[(size_t)l * SPAT];
                float du = d * uv;
                float y = 0.f;
#pragma unroll
                for (int n = 0; n < NST; n++) {
                    float e = __expf(d * __ldg(&arow[n]));
                    hs[n] = e * hs[n] + du * sB[l * NST + n];
                    y += hs[n] * sC[l * NST + n];
                }
                yptr[(size_t)l * SPAT] = y + Dv * uv;
            }
        }
    }
}

// ---------------- combine dirs + LayerNorm(dg) + gelu(z) gate; write [b][dg][l] ----------------
__global__ void __launch_bounds__(256) ln_kernel(
    const float* __restrict__ ys, const float* __restrict__ xz,
    const float* __restrict__ ln_g, const float* __restrict__ ln_b,
    float* __restrict__ ygT)
{
    __shared__ float tY[64 * 129];
    __shared__ float s_mu[64], s_rs[64];

    int lt = blockIdx.x;
    int b  = blockIdx.y;
    int t  = threadIdx.x;

    const float* ysA = ys + ((size_t)b * DI + lt * 64) * SPAT;
    const float* ysB = ys + (size_t)BL * SPAT + (size_t)b * DI * SPAT;

    for (int idx = t; idx < 64 * SPAT; idx += 256) {
        int l = idx / SPAT, dg = idx - l * SPAT;
        int gl = lt * 64 + l;
        float v = ysA[(size_t)l * SPAT + dg] + ysB[(size_t)(255 - gl) * SPAT + dg];
        tY[l * 129 + dg] = v;
    }
    __syncthreads();

    int w = t >> 5, lane = t & 31;
    for (int l = w * 8; l < w * 8 + 8; l++) {
        float s1 = 0.f, s2 = 0.f;
        for (int dg = lane; dg < SPAT; dg += 32) {
            float v = tY[l * 129 + dg];
            s1 += v; s2 += v * v;
        }
#pragma unroll
        for (int off = 16; off > 0; off >>= 1) {
            s1 += __shfl_xor_sync(0xffffffffu, s1, off);
            s2 += __shfl_xor_sync(0xffffffffu, s2, off);
        }
        if (lane == 0) {
            float mu = s1 * (1.f / SPAT);
            float var = s2 * (1.f / SPAT) - mu * mu;
            s_mu[l] = mu;
            s_rs[l] = rsqrtf(var + 1e-5f);
        }
    }
    __syncthreads();

    for (int idx = t; idx < SPAT * 64; idx += 256) {
        int dg = idx >> 6, l = idx & 63;
        int gl = lt * 64 + l;
        float v = (tY[l * 129 + dg] - s_mu[l]) * s_rs[l] * ln_g[dg] + ln_b[dg];
        float zv = xz[((size_t)b * SPAT + dg) * 512 + 256 + gl];
        float gz = 0.5f * zv * (1.f + erff(zv * 0.7071067811865475f));
        ygT[((size_t)b * SPAT + dg) * DI + gl] = v * gz;
    }
}

// ---------------- launcher ----------------
extern "C" void kernel_launch(void* const* d_in, const int* in_sizes, int n_in,
                              void* d_out, int out_size)
{
    const float* x         = (const float*)d_in[0];
    const float* in_proj_w = (const float*)d_in[1];
    const float* conv_w    = (const float*)d_in[2];
    const float* conv_b    = (const float*)d_in[3];
    const float* x_proj_w  = (const float*)d_in[4];
    const float* dt_proj_w = (const float*)d_in[5];
    const float* dt_proj_b = (const float*)d_in[6];
    const float* A_logs    = (const float*)d_in[7];
    const float* Ds        = (const float*)d_in[8];
    const float* ln_g      = (const float*)d_in[9];
    const float* ln_b      = (const float*)d_in[10];
    const float* out_proj_w= (const float*)d_in[11];
    float* out = (float*)d_out;

    float *p_xz, *p_u, *p_xdbl2, *p_delta, *p_ys, *p_ygT;
    cudaGetSymbolAddress((void**)&p_xz,    g_xz);
    cudaGetSymbolAddress((void**)&p_u,     g_u);
    cudaGetSymbolAddress((void**)&p_xdbl2, g_xdbl2);
    cudaGetSymbolAddress((void**)&p_delta, g_delta);
    cudaGetSymbolAddress((void**)&p_ys,    g_ys);
    cudaGetSymbolAddress((void**)&p_ygT,   g_ygT);

    cudaFuncSetAttribute(scan_kernel,
                         cudaFuncAttributeMaxDynamicSharedMemorySize,
                         SCAN_SMEM_BYTES);

    // K1: xz = x @ in_proj_w.T   [15488,128] x [512,128]^T
    gemm_tc<1><<<dim3(ROWS / 128, 4), 256>>>(
        x, in_proj_w, p_xz, 512, DM, DM, DM, 512);

    // K2: depthwise conv + SiLU -> u[b][l][dg]
    conv_kernel<<<dim3(4, BATCH), 256>>>(p_xz, conv_w, conv_b, p_u);

    // K3: merged x_dbl: [32768,121] x [80,121]^T -> [32768,80]
    gemm_tc<0><<<dim3(BL / 128, 1), 256>>>(
        p_u, x_proj_w, p_xdbl2, C80, SPAT, SPAT, SPAT, C80);

    // K3b: delta = softplus(dt-proj)  (high-occupancy elementwise-ish kernel)
    delta_kernel<<<dim3(BATCH, 2), 512>>>(p_xdbl2, dt_proj_w, dt_proj_b, p_delta);

    // K4: chunk-parallel selective scan (packed f32x2)
    scan_kernel<<<dim3(BATCH, 2), 512, SCAN_SMEM_BYTES>>>(
        p_xdbl2, p_u, p_delta, A_logs, Ds, p_ys);

    // K5: combine directions + LN + gelu(z) gate -> ygT[b*121+dg][l]
    ln_kernel<<<dim3(4, BATCH), 256>>>(p_ys, p_xz, ln_g, ln_b, p_ygT);

    // K6: out = ygT @ out_proj_w.T   [15488,256] x [128,256]^T
    gemm_tc<1><<<dim3(ROWS / 128, 1), 256>>>(
        p_ygT, out_proj_w, out, DM, DI, DI, DI, DM);
}

// round 15
// speedup vs baseline: 2.6444x; 1.0529x over previous
#include <cuda_runtime.h>
#include <cuda_bf16.h>
#include <math.h>

// ---------------- problem constants ----------------
#define BATCH 128
#define SPAT  121          // H*W = d_spectral (dg)
#define SPP   128          // padded row stride for u/delta
#define DM    128          // d_model
#define DI    256          // d_inner = scan length L
#define NST   16           // d_state
#define RTK   8            // dt_rank
#define C40   40           // dt_rank + 2*NST per direction
#define C80   80           // merged both directions
#define ROWS  (BATCH*SPAT) // 15488
#define BL    (BATCH*DI)   // 32768 rows for per-(b,l) GEMMs

#define NCHUNK 4
#define LCHUNK (DI/NCHUNK) // 64

// scan dynamic smem (floats): sB@0[4096] sC@4096[4096] sH@8192[4*121*18=8712] sS@16904[512]
#define SH_B  0
#define SH_C  4096
#define SH_H  8192
#define SH_S  16904
#define SCAN_SMEM_FLOATS (SH_S + 512)
#define SCAN_SMEM_BYTES  (SCAN_SMEM_FLOATS * 4)

// ---------------- scratch (device globals; no allocation allowed) ----------------
__device__ float g_xz   [ROWS*512];          // in_proj output [b*121+s][512]
__device__ float g_u    [(size_t)BL*SPP];    // conv+silu out, [b][l][dg] (pad 128)
__device__ float g_xw   [C80*SPP];           // x_proj_w zero-padded to [80][128]
__device__ float g_xdbl2[(size_t)BL*C80];    // merged x_dbl   [b*256+l][80]
__device__ float g_delta[2ull*BL*SPP];       // softplus dt    [k][b*256+l][dg] (pad 128)
__device__ float g_ys   [2ull*BL*SPAT];      // scan out       [k][b*256+l][dg]
__device__ float g_ygT  [ROWS*DI];           // LN*gelu(z)     [b*121+dg][l]

// ---------------- packed f32x2 helpers (Blackwell FFMA2 path) ----------------
typedef unsigned long long ull;
__device__ __forceinline__ ull pk2(float lo, float hi) {
    ull r; asm("mov.b64 %0, {%1, %2};" : "=l"(r) : "f"(lo), "f"(hi)); return r;
}
__device__ __forceinline__ float2 upk2(ull v) {
    float2 f; asm("mov.b64 {%0, %1}, %2;" : "=f"(f.x), "=f"(f.y) : "l"(v)); return f;
}
__device__ __forceinline__ ull fma2(ull a, ull b, ull c) {
    ull d; asm("fma.rn.f32x2 %0, %1, %2, %3;" : "=l"(d) : "l"(a), "l"(b), "l"(c)); return d;
}
__device__ __forceinline__ ull mul2(ull a, ull b) {
    ull d; asm("mul.rn.f32x2 %0, %1, %2;" : "=l"(d) : "l"(a), "l"(b)); return d;
}

// fast softplus: max(x,0) + log(1+exp(-|x|)), MUFU-based
__device__ __forceinline__ float softplus_fast(float x) {
    return fmaxf(x, 0.f) + __logf(1.f + __expf(-fabsf(x)));
}

// ---------------- tf32 tensor-core GEMM ----------------
__device__ __forceinline__ unsigned f2tf32(float v) {
    unsigned r;
    asm("cvt.rna.tf32.f32 %0, %1;" : "=r"(r) : "f"(v));
    return r;
}

__device__ __forceinline__ void mma_tf32(float (&d)[4], const unsigned (&a)[4],
                                         const unsigned (&b)[2]) {
    asm volatile(
        "mma.sync.aligned.m16n8k8.row.col.f32.tf32.tf32.f32 "
        "{%0,%1,%2,%3}, {%4,%5,%6,%7}, {%8,%9}, {%0,%1,%2,%3};\n"
        : "+f"(d[0]), "+f"(d[1]), "+f"(d[2]), "+f"(d[3])
        : "r"(a[0]), "r"(a[1]), "r"(a[2]), "r"(a[3]), "r"(b[0]), "r"(b[1]));
}

#define SPAD 44

__global__ void __launch_bounds__(256) gemm_tc(
    const float* __restrict__ A, const float* __restrict__ W,
    float* __restrict__ C, int N, int K, int lda, int ldb, int ldc)
{
    __shared__ unsigned As[128][SPAD];
    __shared__ unsigned Bs[128][SPAD];

    const int t    = threadIdx.x;
    const int wid  = t >> 5, lane = t & 31;
    const int g    = lane >> 2, tig = lane & 3;
    const int wm   = wid >> 1, wn = wid & 1;
    const int rowBase = blockIdx.x * 128;
    const int colBase = blockIdx.y * 128;

    float acc[2][8][4];
#pragma unroll
    for (int mt = 0; mt < 2; mt++)
#pragma unroll
        for (int nt = 0; nt < 8; nt++)
#pragma unroll
            for (int q = 0; q < 4; q++) acc[mt][nt][q] = 0.f;

    for (int k0 = 0; k0 < K; k0 += 32) {
#pragma unroll
        for (int j = 0; j < 4; j++) {
            int i  = t + j * 256;
            int r  = i >> 3;
            int c4 = (i & 7) << 2;
            float4 va = *(const float4*)&A[(size_t)(rowBase + r) * lda + k0 + c4];
            As[r][c4 + 0] = f2tf32(va.x);
            As[r][c4 + 1] = f2tf32(va.y);
            As[r][c4 + 2] = f2tf32(va.z);
            As[r][c4 + 3] = f2tf32(va.w);
            float4 vb;
            if (colBase + r < N)
                vb = *(const float4*)&W[(size_t)(colBase + r) * ldb + k0 + c4];
            else
                vb = make_float4(0.f, 0.f, 0.f, 0.f);
            Bs[r][c4 + 0] = f2tf32(vb.x);
            Bs[r][c4 + 1] = f2tf32(vb.y);
            Bs[r][c4 + 2] = f2tf32(vb.z);
            Bs[r][c4 + 3] = f2tf32(vb.w);
        }
        __syncthreads();

#pragma unroll
        for (int ks = 0; ks < 4; ks++) {
            const int kk = ks * 8;
            unsigned af[2][4], bf[8][2];
#pragma unroll
            for (int mt = 0; mt < 2; mt++) {
                int row = wm * 32 + mt * 16 + g;
                af[mt][0] = As[row    ][kk + tig];
                af[mt][1] = As[row + 8][kk + tig];
                af[mt][2] = As[row    ][kk + tig + 4];
                af[mt][3] = As[row + 8][kk + tig + 4];
            }
#pragma unroll
            for (int nt = 0; nt < 8; nt++) {
                int col = wn * 64 + nt * 8 + g;
                bf[nt][0] = Bs[col][kk + tig];
                bf[nt][1] = Bs[col][kk + tig + 4];
            }
#pragma unroll
            for (int mt = 0; mt < 2; mt++)
#pragma unroll
                for (int nt = 0; nt < 8; nt++)
                    mma_tf32(acc[mt][nt], af[mt], bf[nt]);
        }
        __syncthreads();
    }

#pragma unroll
    for (int mt = 0; mt < 2; mt++) {
#pragma unroll
        for (int nt = 0; nt < 8; nt++) {
            int row0 = rowBase + wm * 32 + mt * 16 + g;
            int col0 = colBase + wn * 64 + nt * 8 + 2 * tig;
            if (col0 < N) {
                C[(size_t)row0 * ldc + col0]           = acc[mt][nt][0];
                C[(size_t)(row0 + 8) * ldc + col0]     = acc[mt][nt][2];
            }
            if (col0 + 1 < N) {
                C[(size_t)row0 * ldc + col0 + 1]       = acc[mt][nt][1];
                C[(size_t)(row0 + 8) * ldc + col0 + 1] = acc[mt][nt][3];
            }
        }
    }
}

// ---------------- pack x_proj_w [80][121] -> zero-padded [80][128] ----------------
__global__ void __launch_bounds__(256) pack_w_kernel(
    const float* __restrict__ x_proj_w, float* __restrict__ xw)
{
    int i = blockIdx.x * 256 + threadIdx.x;   // 0 .. 80*128-1
    if (i >= C80 * SPP) return;
    int r = i >> 7, c = i & 127;
    xw[i] = (c < SPAT) ? x_proj_w[r * SPAT + c] : 0.f;
}

// ---------------- depthwise 3x3 conv + SiLU, xz[:, :256] -> u[b][l][dg](pad128) ----------------
__global__ void __launch_bounds__(256) conv_kernel(
    const float* __restrict__ xz, const float* __restrict__ conv_w,
    const float* __restrict__ conv_b, float* __restrict__ u)
{
    __shared__ float s_in[SPAT * 65];
    int ct = blockIdx.x;
    int b  = blockIdx.y;
    int t  = threadIdx.x;

    for (int idx = t; idx < SPAT * 64; idx += 256) {
        int s = idx >> 6, c = idx & 63;
        s_in[s * 65 + c] = xz[((size_t)b * SPAT + s) * 512 + ct * 64 + c];
    }
    __syncthreads();

    size_t base = ((size_t)b * DI + ct * 64) * SPP;
    for (int idx = t; idx < 64 * SPP; idx += 256) {
        int c = idx >> 7;
        int s = idx & 127;
        float sv = 0.f;
        if (s < SPAT) {
            int i = s / 11, j = s - i * 11;
            int ch = ct * 64 + c;
            float acc = conv_b[ch];
#pragma unroll
            for (int ti = 0; ti < 3; ti++) {
                int ii = i + ti - 1;
                if ((unsigned)ii < 11u) {
#pragma unroll
                    for (int tj = 0; tj < 3; tj++) {
                        int jj = j + tj - 1;
                        if ((unsigned)jj < 11u)
                            acc += s_in[(ii * 11 + jj) * 65 + c] * conv_w[ch * 9 + ti * 3 + tj];
                    }
                }
            }
            sv = acc / (1.f + __expf(-acc));
        }
        u[base + idx] = sv;
    }
}

// ---------------- delta precompute: softplus(dts @ dt_proj_w^T + b) ----------------
__global__ void __launch_bounds__(512) delta_kernel(
    const float* __restrict__ xdbl2, const float* __restrict__ dt_proj_w,
    const float* __restrict__ dt_proj_b, float* __restrict__ delta)
{
    __shared__ float sdt[DI][RTK];   // 8 KB

    const int b = blockIdx.x;
    const int k = blockIdx.y;
    const int tid = threadIdx.x;
    const int lgrp = tid >> 7;
    const int dg = tid & 127;
    const bool act = dg < SPAT;

    const float* xd = xdbl2 + ((size_t)b * DI) * C80 + k * C40;
    for (int idx = tid; idx < DI * RTK; idx += 512) {
        int l = idx >> 3, r = idx & 7;
        sdt[l][r] = __ldg(&xd[(size_t)l * C80 + r]);
    }

    float w8[RTK];
    float bias = 0.f;
    if (act) {
        const float* wrow = dt_proj_w + ((size_t)k * SPAT + dg) * RTK;
#pragma unroll
        for (int r = 0; r < RTK; r++) w8[r] = wrow[r];
        bias = dt_proj_b[k * SPAT + dg];
    }
    __syncthreads();

    if (!act) return;
    float* dout = delta + ((size_t)k * BL + (size_t)b * DI) * SPP + dg;
    for (int l = lgrp; l < DI; l += 4) {
        float dr = bias;
#pragma unroll
        for (int r = 0; r < RTK; r++) dr = fmaf(w8[r], sdt[l][r], dr);
        dout[(size_t)l * SPP] = softplus_fast(dr);
    }
}

// ---------------- chunk-parallel selective scan (f32x2 + prefetched loads) ----------------
__global__ void __launch_bounds__(512, 2) scan_kernel(
    const float* __restrict__ xdbl2, const float* __restrict__ u,
    const float* __restrict__ delta,
    const float* __restrict__ A_logs, const float* __restrict__ Ds,
    float* __restrict__ ys)
{
    extern __shared__ float sm[];
    float* sB = sm + SH_B;      // [l*16+n]
    float* sC = sm + SH_C;      // [l*16+n]
    float* sH = sm + SH_H;      // [(c*121+dg)*18+n]
    float* sS = sm + SH_S;      // [c*128+dg]

    const int b   = blockIdx.x;
    const int k   = blockIdx.y;
    const int tid = threadIdx.x;
    const int c   = tid >> 7;
    const int dg  = tid & 127;
    const bool act = dg < SPAT;

    // stage B,C (cols 8..39 of this dir's 40-wide slice)
    const float* xd = xdbl2 + ((size_t)b * DI) * C80 + k * C40 + RTK;
    for (int idx = tid; idx < DI * 32; idx += 512) {
        int l = idx >> 5, cc = idx & 31;
        float v = __ldg(&xd[(size_t)l * C80 + cc]);
        if (cc < NST) sB[l * NST + cc] = v;
        else          sC[l * NST + (cc - NST)] = v;
    }

    float a1 = 0.f, Dv = 0.f;
    bool geo = false;
    const float* arow = A_logs + ((size_t)k * SPAT + (act ? dg : 0)) * NST;
    if (act) {
        a1 = -expf(arow[0]);
        geo = true;
#pragma unroll
        for (int n = 0; n < NST; n++) {
            float an = -expf(arow[n]);
            float tgt = (float)(n + 1) * a1;
            if (fabsf(an - tgt) > 1e-5f * (float)(n + 1) * fabsf(a1)) geo = false;
        }
        Dv = Ds[k * SPAT + dg];
    }
    __syncthreads();

    const float* uptr = u     + ((size_t)b * DI) * SPP + dg;
    const float* dptr = delta + ((size_t)k * BL + (size_t)b * DI) * SPP + dg;
    const int l_beg = c * LCHUNK;
    const int l_end = l_beg + LCHUNK;

    // ---- Phase A: local scan, chunks 0..2 ----
    if (act && c < NCHUNK - 1) {
        ull hh2[8];
#pragma unroll
        for (int j = 0; j < 8; j++) hh2[j] = pk2(0.f, 0.f);
        float S = 0.f;
        if (geo) {
            float dc = dptr[(size_t)l_beg * SPP];
            float uc = uptr[(size_t)l_beg * SPP];
            for (int l = l_beg; l < l_end; l++) {
                float d = dc, uv = uc;
                if (l + 1 < l_end) {
                    dc = dptr[(size_t)(l + 1) * SPP];
                    uc = uptr[(size_t)(l + 1) * SPP];
                }
                S += d;
                float du = d * uv;
                float q1 = __expf(d * a1);
                float q2 = q1 * q1;
                ull e2 = pk2(q1, q2), qq = pk2(q2, q2), du2 = pk2(du, du);
                const float4* B4 = (const float4*)&sB[l * NST];
#pragma unroll
                for (int jj = 0; jj < 4; jj++) {
                    float4 bb = B4[jj];
                    hh2[2*jj]   = fma2(e2, hh2[2*jj],   mul2(du2, pk2(bb.x, bb.y)));
                    e2 = mul2(e2, qq);
                    hh2[2*jj+1] = fma2(e2, hh2[2*jj+1], mul2(du2, pk2(bb.z, bb.w)));
                    e2 = mul2(e2, qq);
                }
            }
        } else {
            float hs[NST];
#pragma unroll
            for (int n = 0; n < NST; n++) hs[n] = 0.f;
            for (int l = l_beg; l < l_end; l++) {
                float d  = dptr[(size_t)l * SPP];
                float uv = uptr[(size_t)l * SPP];
                S += d;
                float du = d * uv;
#pragma unroll
                for (int n = 0; n < NST; n++) {
                    float e = __expf(d * __ldg(&arow[n]));
                    hs[n] = e * hs[n] + du * sB[l * NST + n];
                }
            }
#pragma unroll
            for (int j = 0; j < 8; j++) hh2[j] = pk2(hs[2*j], hs[2*j+1]);
        }
        float* hrow = &sH[(size_t)(c * SPAT + dg) * 18];
#pragma unroll
        for (int j = 0; j < 8; j++) {
            float2 hv = upk2(hh2[j]);
            hrow[2*j] = hv.x; hrow[2*j+1] = hv.y;
        }
        sS[c * 128 + dg] = S;
    }
    __syncthreads();

    // ---- Combine: prefix over chunk ends ----
    if (act && c == 0) {
        for (int cc = 1; cc < NCHUNK - 1; cc++) {
            float Sc = sS[cc * 128 + dg];
            float* cur = &sH[(size_t)(cc * SPAT + dg) * 18];
            float* prv = &sH[(size_t)((cc - 1) * SPAT + dg) * 18];
            if (geo) {
                float p1 = __expf(Sc * a1);
                float e = 1.f;
#pragma unroll
                for (int n = 0; n < NST; n++) {
                    e *= p1;
                    cur[n] += e * prv[n];
                }
            } else {
#pragma unroll
                for (int n = 0; n < NST; n++) {
                    float e = __expf(Sc * __ldg(&arow[n]));
                    cur[n] += e * prv[n];
                }
            }
        }
    }
    __syncthreads();

    // ---- Phase C: full scan seeded with true h0 ----
    if (act) {
        ull hh2[8];
        if (c == 0) {
#pragma unroll
            for (int j = 0; j < 8; j++) hh2[j] = pk2(0.f, 0.f);
        } else {
            const float* hrow = &sH[(size_t)((c - 1) * SPAT + dg) * 18];
#pragma unroll
            for (int j = 0; j < 8; j++) hh2[j] = pk2(hrow[2*j], hrow[2*j+1]);
        }
        float* yptr = ys + ((size_t)k * BL + (size_t)b * DI) * SPAT + dg;
        if (geo) {
            float dc = dptr[(size_t)l_beg * SPP];
            float uc = uptr[(size_t)l_beg * SPP];
            for (int l = l_beg; l < l_end; l++) {
                float d = dc, uv = uc;
                if (l + 1 < l_end) {
                    dc = dptr[(size_t)(l + 1) * SPP];
                    uc = uptr[(size_t)(l + 1) * SPP];
                }
                float du = d * uv;
                float q1 = __expf(d * a1);
                float q2 = q1 * q1;
                ull e2 = pk2(q1, q2), qq = pk2(q2, q2), du2 = pk2(du, du);
                ull yacc = pk2(0.f, 0.f);
                const float4* B4 = (const float4*)&sB[l * NST];
                const float4* C4 = (const float4*)&sC[l * NST];
#pragma unroll
                for (int jj = 0; jj < 4; jj++) {
                    float4 bb = B4[jj];
                    float4 cv = C4[jj];
                    hh2[2*jj]   = fma2(e2, hh2[2*jj],   mul2(du2, pk2(bb.x, bb.y)));
                    yacc        = fma2(hh2[2*jj], pk2(cv.x, cv.y), yacc);
                    e2 = mul2(e2, qq);
                    hh2[2*jj+1] = fma2(e2, hh2[2*jj+1], mul2(du2, pk2(bb.z, bb.w)));
                    yacc        = fma2(hh2[2*jj+1], pk2(cv.z, cv.w), yacc);
                    e2 = mul2(e2, qq);
                }
                float2 yv = upk2(yacc);
                yptr[(size_t)l * SPAT] = yv.x + yv.y + Dv * uv;
            }
        } else {
            float hs[NST];
#pragma unroll
            for (int j = 0; j < 8; j++) {
                float2 hv = upk2(hh2[j]);
                hs[2*j] = hv.x; hs[2*j+1] = hv.y;
            }
            for (int l = l_beg; l < l_end; l++) {
                float d  = dptr[(size_t)l * SPP];
                float uv = uptr[(size_t)l * SPP];
                float du = d * uv;
                float y = 0.f;
#pragma unroll
                for (int n = 0; n < NST; n++) {
                    float e = __expf(d * __ldg(&arow[n]));
                    hs[n] = e * hs[n] + du * sB[l * NST + n];
                    y += hs[n] * sC[l * NST + n];
                }
                yptr[(size_t)l * SPAT] = y + Dv * uv;
            }
        }
    }
}

// ---------------- combine dirs + LayerNorm(dg) + gelu(z) gate; write [b][dg][l] ----------------
__global__ void __launch_bounds__(256) ln_kernel(
    const float* __restrict__ ys, const float* __restrict__ xz,
    const float* __restrict__ ln_g, const float* __restrict__ ln_b,
    float* __restrict__ ygT)
{
    __shared__ float tY[64 * 129];
    __shared__ float s_mu[64], s_rs[64];

    int lt = blockIdx.x;
    int b  = blockIdx.y;
    int t  = threadIdx.x;

    const float* ysA = ys + ((size_t)b * DI + lt * 64) * SPAT;
    const float* ysB = ys + (size_t)BL * SPAT + (size_t)b * DI * SPAT;

    for (int idx = t; idx < 64 * SPAT; idx += 256) {
        int l = idx / SPAT, dg = idx - l * SPAT;
        int gl = lt * 64 + l;
        float v = ysA[(size_t)l * SPAT + dg] + ysB[(size_t)(255 - gl) * SPAT + dg];
        tY[l * 129 + dg] = v;
    }
    __syncthreads();

    int w = t >> 5, lane = t & 31;
    for (int l = w * 8; l < w * 8 + 8; l++) {
        float s1 = 0.f, s2 = 0.f;
        for (int dg = lane; dg < SPAT; dg += 32) {
            float v = tY[l * 129 + dg];
            s1 += v; s2 += v * v;
        }
#pragma unroll
        for (int off = 16; off > 0; off >>= 1) {
            s1 += __shfl_xor_sync(0xffffffffu, s1, off);
            s2 += __shfl_xor_sync(0xffffffffu, s2, off);
        }
        if (lane == 0) {
            float mu = s1 * (1.f / SPAT);
            float var = s2 * (1.f / SPAT) - mu * mu;
            s_mu[l] = mu;
            s_rs[l] = rsqrtf(var + 1e-5f);
        }
    }
    __syncthreads();

    for (int idx = t; idx < SPAT * 64; idx += 256) {
        int dg = idx >> 6, l = idx & 63;
        int gl = lt * 64 + l;
        float v = (tY[l * 129 + dg] - s_mu[l]) * s_rs[l] * ln_g[dg] + ln_b[dg];
        float zv = xz[((size_t)b * SPAT + dg) * 512 + 256 + gl];
        float gz = 0.5f * zv * (1.f + erff(zv * 0.7071067811865475f));
        ygT[((size_t)b * SPAT + dg) * DI + gl] = v * gz;
    }
}

// ---------------- launcher ----------------
extern "C" void kernel_launch(void* const* d_in, const int* in_sizes, int n_in,
                              void* d_out, int out_size)
{
    const float* x         = (const float*)d_in[0];
    const float* in_proj_w = (const float*)d_in[1];
    const float* conv_w    = (const float*)d_in[2];
    const float* conv_b    = (const float*)d_in[3];
    const float* x_proj_w  = (const float*)d_in[4];
    const float* dt_proj_w = (const float*)d_in[5];
    const float* dt_proj_b = (const float*)d_in[6];
    const float* A_logs    = (const float*)d_in[7];
    const float* Ds        = (const float*)d_in[8];
    const float* ln_g      = (const float*)d_in[9];
    const float* ln_b      = (const float*)d_in[10];
    const float* out_proj_w= (const float*)d_in[11];
    float* out = (float*)d_out;

    float *p_xz, *p_u, *p_xw, *p_xdbl2, *p_delta, *p_ys, *p_ygT;
    cudaGetSymbolAddress((void**)&p_xz,    g_xz);
    cudaGetSymbolAddress((void**)&p_u,     g_u);
    cudaGetSymbolAddress((void**)&p_xw,    g_xw);
    cudaGetSymbolAddress((void**)&p_xdbl2, g_xdbl2);
    cudaGetSymbolAddress((void**)&p_delta, g_delta);
    cudaGetSymbolAddress((void**)&p_ys,    g_ys);
    cudaGetSymbolAddress((void**)&p_ygT,   g_ygT);

    cudaFuncSetAttribute(scan_kernel,
                         cudaFuncAttributeMaxDynamicSharedMemorySize,
                         SCAN_SMEM_BYTES);

    // K0: pack x_proj_w into padded [80][128]
    pack_w_kernel<<<(C80 * SPP + 255) / 256, 256>>>(x_proj_w, p_xw);

    // K1: xz = x @ in_proj_w.T   [15488,128] x [512,128]^T
    gemm_tc<<<dim3(ROWS / 128, 4), 256>>>(
        x, in_proj_w, p_xz, 512, DM, DM, DM, 512);

    // K2: depthwise conv + SiLU -> u[b][l][dg] (stride 128, zero-padded)
    conv_kernel<<<dim3(4, BATCH), 256>>>(p_xz, conv_w, conv_b, p_u);

    // K3: merged x_dbl: [32768,128pad] x [80,128pad]^T -> [32768,80]  (vec path)
    gemm_tc<<<dim3(BL / 128, 1), 256>>>(
        p_u, p_xw, p_xdbl2, C80, SPP, SPP, SPP, C80);

    // K3b: delta = fast-softplus(dt-proj)   (padded stride 128)
    delta_kernel<<<dim3(BATCH, 2), 512>>>(p_xdbl2, dt_proj_w, dt_proj_b, p_delta);

    // K4: chunk-parallel selective scan (f32x2 + prefetch)
    scan_kernel<<<dim3(BATCH, 2), 512, SCAN_SMEM_BYTES>>>(
        p_xdbl2, p_u, p_delta, A_logs, Ds, p_ys);

    // K5: combine directions + LN + gelu(z) gate -> ygT[b*121+dg][l]
    ln_kernel<<<dim3(4, BATCH), 256>>>(p_ys, p_xz, ln_g, ln_b, p_ygT);

    // K6: out = ygT @ out_proj_w.T   [15488,256] x [128,256]^T
    gemm_tc<<<dim3(ROWS / 128, 1), 256>>>(
        p_ygT, out_proj_w, out, DM, DI, DI, DI, DM);
}

// round 16
// speedup vs baseline: 2.8104x; 1.0628x over previous
#include <cuda_runtime.h>
#include <cuda_bf16.h>
#include <math.h>

// ---------------- problem constants ----------------
#define BATCH 128
#define SPAT  121          // H*W = d_spectral (dg)
#define SPP   128          // padded row stride for u/delta
#define DM    128          // d_model
#define DI    256          // d_inner = scan length L
#define NST   16           // d_state
#define RTK   8            // dt_rank
#define C40   40           // dt_rank + 2*NST per direction
#define C80   80           // merged both directions
#define ROWS  (BATCH*SPAT) // 15488
#define BL    (BATCH*DI)   // 32768 rows for per-(b,l) GEMMs

#define NCHUNK 4
#define LCHUNK (DI/NCHUNK) // 64

// scan dynamic smem (floats)
#define SH_B  0
#define SH_C  4096
#define SH_H  8192
#define SH_S  16904
#define SCAN_SMEM_FLOATS (SH_S + 512)
#define SCAN_SMEM_BYTES  (SCAN_SMEM_FLOATS * 4)

// gemm dynamic smem: 2 buffers x (A,B) x 128 x SPAD floats
#define SPAD 44
#define GT_TILE (128 * SPAD)
#define GT_SMEM_BYTES (2 * 2 * GT_TILE * 4)   // 90112

// ---------------- scratch (device globals; no allocation allowed) ----------------
__device__ float g_xz   [ROWS*512];          // in_proj output [b*121+s][512]
__device__ float g_u    [(size_t)BL*SPP];    // conv+silu out, [b][l][dg] (pad 128)
__device__ float g_xw   [C80*SPP];           // x_proj_w zero-padded to [80][128]
__device__ float g_xdbl2[(size_t)BL*C80];    // merged x_dbl   [b*256+l][80]
__device__ float g_delta[2ull*BL*SPP];       // softplus dt    [k][b*256+l][dg] (pad 128)
__device__ float g_ys   [2ull*BL*SPAT];      // scan out       [k][b*256+l][dg]
__device__ float g_ygT  [ROWS*DI];           // LN*gelu(z)     [b*121+dg][l]

// ---------------- packed f32x2 helpers (Blackwell FFMA2 path) ----------------
typedef unsigned long long ull;
__device__ __forceinline__ ull pk2(float lo, float hi) {
    ull r; asm("mov.b64 %0, {%1, %2};" : "=l"(r) : "f"(lo), "f"(hi)); return r;
}
__device__ __forceinline__ float2 upk2(ull v) {
    float2 f; asm("mov.b64 {%0, %1}, %2;" : "=f"(f.x), "=f"(f.y) : "l"(v)); return f;
}
__device__ __forceinline__ ull fma2(ull a, ull b, ull c) {
    ull d; asm("fma.rn.f32x2 %0, %1, %2, %3;" : "=l"(d) : "l"(a), "l"(b), "l"(c)); return d;
}
__device__ __forceinline__ ull mul2(ull a, ull b) {
    ull d; asm("mul.rn.f32x2 %0, %1, %2;" : "=l"(d) : "l"(a), "l"(b)); return d;
}

// fast softplus: max(x,0) + log(1+exp(-|x|)), MUFU-based
__device__ __forceinline__ float softplus_fast(float x) {
    return fmaxf(x, 0.f) + __logf(1.f + __expf(-fabsf(x)));
}

// ---------------- tf32 tensor-core GEMM (cp.async double-buffered) ----------------
__device__ __forceinline__ unsigned f2tf32(float v) {
    unsigned r;
    asm("cvt.rna.tf32.f32 %0, %1;" : "=r"(r) : "f"(v));
    return r;
}

__device__ __forceinline__ void mma_tf32(float (&d)[4], const unsigned (&a)[4],
                                         const unsigned (&b)[2]) {
    asm volatile(
        "mma.sync.aligned.m16n8k8.row.col.f32.tf32.tf32.f32 "
        "{%0,%1,%2,%3}, {%4,%5,%6,%7}, {%8,%9}, {%0,%1,%2,%3};\n"
        : "+f"(d[0]), "+f"(d[1]), "+f"(d[2]), "+f"(d[3])
        : "r"(a[0]), "r"(a[1]), "r"(a[2]), "r"(b[0]), "r"(a[3]), "r"(b[1])
    );
}

// NOTE on operand order above: keep canonical a0..a3 then b0,b1.
// (Re-written explicitly below to avoid mistakes.)
__device__ __forceinline__ void mma_tf32_c(float (&d)[4], const unsigned (&a)[4],
                                           const unsigned (&b)[2]) {
    asm volatile(
        "mma.sync.aligned.m16n8k8.row.col.f32.tf32.tf32.f32 "
        "{%0,%1,%2,%3}, {%4,%5,%6,%7}, {%8,%9}, {%0,%1,%2,%3};\n"
        : "+f"(d[0]), "+f"(d[1]), "+f"(d[2]), "+f"(d[3])
        : "r"(a[0]), "r"(a[1]), "r"(a[2]), "r"(a[3]), "r"(b[0]), "r"(b[1]));
}

__device__ __forceinline__ void gt_load_tile(
    const float* __restrict__ A, const float* __restrict__ W,
    float* Af, float* Bf,
    int rowBase, int colBase, int N, int k0, int lda, int ldb, int t)
{
#pragma unroll
    for (int j = 0; j < 4; j++) {
        int i  = t + j * 256;            // 0..1023
        int r  = i >> 3;
        int c4 = (i & 7) << 2;
        unsigned da = (unsigned)__cvta_generic_to_shared(&Af[r * SPAD + c4]);
        const float* as = &A[(size_t)(rowBase + r) * lda + k0 + c4];
        asm volatile("cp.async.ca.shared.global [%0], [%1], 16;" :: "r"(da), "l"(as));
        unsigned db = (unsigned)__cvta_generic_to_shared(&Bf[r * SPAD + c4]);
        bool ok = (colBase + r) < N;
        const float* ws = &W[(size_t)(colBase + (ok ? r : 0)) * ldb + k0 + c4];
        if (ok)
            asm volatile("cp.async.ca.shared.global [%0], [%1], 16;" :: "r"(db), "l"(ws));
        else
            asm volatile("cp.async.ca.shared.global [%0], [%1], 16, 0;" :: "r"(db), "l"(ws));
    }
    asm volatile("cp.async.commit_group;");
}

__global__ void __launch_bounds__(256) gemm_tc(
    const float* __restrict__ A, const float* __restrict__ W,
    float* __restrict__ C, int N, int K, int lda, int ldb, int ldc)
{
    extern __shared__ float gsm[];

    const int t    = threadIdx.x;
    const int wid  = t >> 5, lane = t & 31;
    const int g    = lane >> 2, tig = lane & 3;
    const int wm   = wid >> 1, wn = wid & 1;
    const int rowBase = blockIdx.x * 128;
    const int colBase = blockIdx.y * 128;

    float acc[2][8][4];
#pragma unroll
    for (int mt = 0; mt < 2; mt++)
#pragma unroll
        for (int nt = 0; nt < 8; nt++)
#pragma unroll
            for (int q = 0; q < 4; q++) acc[mt][nt][q] = 0.f;

    const int nk = K >> 5;   // K % 32 == 0 at all call sites

    // prefetch tile 0 into buffer 0
    gt_load_tile(A, W, gsm, gsm + GT_TILE, rowBase, colBase, N, 0, lda, ldb, t);

    for (int kt = 0; kt < nk; kt++) {
        const int buf = kt & 1;
        float* Af = gsm + buf * 2 * GT_TILE;
        float* Bf = Af + GT_TILE;

        if (kt + 1 < nk) {
            float* Af2 = gsm + (buf ^ 1) * 2 * GT_TILE;
            gt_load_tile(A, W, Af2, Af2 + GT_TILE,
                         rowBase, colBase, N, (kt + 1) * 32, lda, ldb, t);
            asm volatile("cp.async.wait_group 1;");
        } else {
            asm volatile("cp.async.wait_group 0;");
        }
        __syncthreads();

#pragma unroll
        for (int ks = 0; ks < 4; ks++) {
            const int kk = ks * 8;
            unsigned af[2][4], bf[8][2];
#pragma unroll
            for (int mt = 0; mt < 2; mt++) {
                int row = wm * 32 + mt * 16 + g;
                af[mt][0] = f2tf32(Af[ row      * SPAD + kk + tig]);
                af[mt][1] = f2tf32(Af[(row + 8) * SPAD + kk + tig]);
                af[mt][2] = f2tf32(Af[ row      * SPAD + kk + tig + 4]);
                af[mt][3] = f2tf32(Af[(row + 8) * SPAD + kk + tig + 4]);
            }
#pragma unroll
            for (int nt = 0; nt < 8; nt++) {
                int col = wn * 64 + nt * 8 + g;
                bf[nt][0] = f2tf32(Bf[col * SPAD + kk + tig]);
                bf[nt][1] = f2tf32(Bf[col * SPAD + kk + tig + 4]);
            }
#pragma unroll
            for (int mt = 0; mt < 2; mt++)
#pragma unroll
                for (int nt = 0; nt < 8; nt++)
                    mma_tf32_c(acc[mt][nt], af[mt], bf[nt]);
        }
        __syncthreads();   // all warps done reading buf before tile kt+2 overwrites it
    }

#pragma unroll
    for (int mt = 0; mt < 2; mt++) {
#pragma unroll
        for (int nt = 0; nt < 8; nt++) {
            int row0 = rowBase + wm * 32 + mt * 16 + g;
            int col0 = colBase + wn * 64 + nt * 8 + 2 * tig;
            if (col0 < N) {
                C[(size_t)row0 * ldc + col0]           = acc[mt][nt][0];
                C[(size_t)(row0 + 8) * ldc + col0]     = acc[mt][nt][2];
            }
            if (col0 + 1 < N) {
                C[(size_t)row0 * ldc + col0 + 1]       = acc[mt][nt][1];
                C[(size_t)(row0 + 8) * ldc + col0 + 1] = acc[mt][nt][3];
            }
        }
    }
}

// ---------------- pack x_proj_w [80][121] -> zero-padded [80][128] ----------------
__global__ void __launch_bounds__(256) pack_w_kernel(
    const float* __restrict__ x_proj_w, float* __restrict__ xw)
{
    int i = blockIdx.x * 256 + threadIdx.x;
    if (i >= C80 * SPP) return;
    int r = i >> 7, c = i & 127;
    xw[i] = (c < SPAT) ? x_proj_w[r * SPAT + c] : 0.f;
}

// ---------------- depthwise 3x3 conv + SiLU, xz[:, :256] -> u[b][l][dg](pad128) ----------------
__global__ void __launch_bounds__(256) conv_kernel(
    const float* __restrict__ xz, const float* __restrict__ conv_w,
    const float* __restrict__ conv_b, float* __restrict__ u)
{
    __shared__ float s_in[SPAT * 65];
    int ct = blockIdx.x;
    int b  = blockIdx.y;
    int t  = threadIdx.x;

    for (int idx = t; idx < SPAT * 64; idx += 256) {
        int s = idx >> 6, c = idx & 63;
        s_in[s * 65 + c] = xz[((size_t)b * SPAT + s) * 512 + ct * 64 + c];
    }
    __syncthreads();

    size_t base = ((size_t)b * DI + ct * 64) * SPP;
    for (int idx = t; idx < 64 * SPP; idx += 256) {
        int c = idx >> 7;
        int s = idx & 127;
        float sv = 0.f;
        if (s < SPAT) {
            int i = s / 11, j = s - i * 11;
            int ch = ct * 64 + c;
            float acc = conv_b[ch];
#pragma unroll
            for (int ti = 0; ti < 3; ti++) {
                int ii = i + ti - 1;
                if ((unsigned)ii < 11u) {
#pragma unroll
                    for (int tj = 0; tj < 3; tj++) {
                        int jj = j + tj - 1;
                        if ((unsigned)jj < 11u)
                            acc += s_in[(ii * 11 + jj) * 65 + c] * conv_w[ch * 9 + ti * 3 + tj];
                    }
                }
            }
            sv = acc / (1.f + __expf(-acc));
        }
        u[base + idx] = sv;
    }
}

// ---------------- delta precompute: softplus(dts @ dt_proj_w^T + b) ----------------
__global__ void __launch_bounds__(512) delta_kernel(
    const float* __restrict__ xdbl2, const float* __restrict__ dt_proj_w,
    const float* __restrict__ dt_proj_b, float* __restrict__ delta)
{
    __shared__ float sdt[DI][RTK];

    const int b = blockIdx.x;
    const int k = blockIdx.y;
    const int tid = threadIdx.x;
    const int lgrp = tid >> 7;
    const int dg = tid & 127;
    const bool act = dg < SPAT;

    const float* xd = xdbl2 + ((size_t)b * DI) * C80 + k * C40;
    for (int idx = tid; idx < DI * RTK; idx += 512) {
        int l = idx >> 3, r = idx & 7;
        sdt[l][r] = __ldg(&xd[(size_t)l * C80 + r]);
    }

    float w8[RTK];
    float bias = 0.f;
    if (act) {
        const float* wrow = dt_proj_w + ((size_t)k * SPAT + dg) * RTK;
#pragma unroll
        for (int r = 0; r < RTK; r++) w8[r] = wrow[r];
        bias = dt_proj_b[k * SPAT + dg];
    }
    __syncthreads();

    if (!act) return;
    float* dout = delta + ((size_t)k * BL + (size_t)b * DI) * SPP + dg;
    for (int l = lgrp; l < DI; l += 4) {
        float dr = bias;
#pragma unroll
        for (int r = 0; r < RTK; r++) dr = fmaf(w8[r], sdt[l][r], dr);
        dout[(size_t)l * SPP] = softplus_fast(dr);
    }
}

// ---------------- chunk-parallel selective scan (f32x2 + prefetched loads) ----------------
__global__ void __launch_bounds__(512, 2) scan_kernel(
    const float* __restrict__ xdbl2, const float* __restrict__ u,
    const float* __restrict__ delta,
    const float* __restrict__ A_logs, const float* __restrict__ Ds,
    float* __restrict__ ys)
{
    extern __shared__ float sm[];
    float* sB = sm + SH_B;
    float* sC = sm + SH_C;
    float* sH = sm + SH_H;
    float* sS = sm + SH_S;

    const int b   = blockIdx.x;
    const int k   = blockIdx.y;
    const int tid = threadIdx.x;
    const int c   = tid >> 7;
    const int dg  = tid & 127;
    const bool act = dg < SPAT;

    const float* xd = xdbl2 + ((size_t)b * DI) * C80 + k * C40 + RTK;
    for (int idx = tid; idx < DI * 32; idx += 512) {
        int l = idx >> 5, cc = idx & 31;
        float v = __ldg(&xd[(size_t)l * C80 + cc]);
        if (cc < NST) sB[l * NST + cc] = v;
        else          sC[l * NST + (cc - NST)] = v;
    }

    float a1 = 0.f, Dv = 0.f;
    bool geo = false;
    const float* arow = A_logs + ((size_t)k * SPAT + (act ? dg : 0)) * NST;
    if (act) {
        a1 = -expf(arow[0]);
        geo = true;
#pragma unroll
        for (int n = 0; n < NST; n++) {
            float an = -expf(arow[n]);
            float tgt = (float)(n + 1) * a1;
            if (fabsf(an - tgt) > 1e-5f * (float)(n + 1) * fabsf(a1)) geo = false;
        }
        Dv = Ds[k * SPAT + dg];
    }
    __syncthreads();

    const float* uptr = u     + ((size_t)b * DI) * SPP + dg;
    const float* dptr = delta + ((size_t)k * BL + (size_t)b * DI) * SPP + dg;
    const int l_beg = c * LCHUNK;
    const int l_end = l_beg + LCHUNK;

    if (act && c < NCHUNK - 1) {
        ull hh2[8];
#pragma unroll
        for (int j = 0; j < 8; j++) hh2[j] = pk2(0.f, 0.f);
        float S = 0.f;
        if (geo) {
            float dc = dptr[(size_t)l_beg * SPP];
            float uc = uptr[(size_t)l_beg * SPP];
            for (int l = l_beg; l < l_end; l++) {
                float d = dc, uv = uc;
                if (l + 1 < l_end) {
                    dc = dptr[(size_t)(l + 1) * SPP];
                    uc = uptr[(size_t)(l + 1) * SPP];
                }
                S += d;
                float du = d * uv;
                float q1 = __expf(d * a1);
                float q2 = q1 * q1;
                ull e2 = pk2(q1, q2), qq = pk2(q2, q2), du2 = pk2(du, du);
                const float4* B4 = (const float4*)&sB[l * NST];
#pragma unroll
                for (int jj = 0; jj < 4; jj++) {
                    float4 bb = B4[jj];
                    hh2[2*jj]   = fma2(e2, hh2[2*jj],   mul2(du2, pk2(bb.x, bb.y)));
                    e2 = mul2(e2, qq);
                    hh2[2*jj+1] = fma2(e2, hh2[2*jj+1], mul2(du2, pk2(bb.z, bb.w)));
                    e2 = mul2(e2, qq);
                }
            }
        } else {
            float hs[NST];
#pragma unroll
            for (int n = 0; n < NST; n++) hs[n] = 0.f;
            for (int l = l_beg; l < l_end; l++) {
                float d  = dptr[(size_t)l * SPP];
                float uv = uptr[(size_t)l * SPP];
                S += d;
                float du = d * uv;
#pragma unroll
                for (int n = 0; n < NST; n++) {
                    float e = __expf(d * __ldg(&arow[n]));
                    hs[n] = e * hs[n] + du * sB[l * NST + n];
                }
            }
#pragma unroll
            for (int j = 0; j < 8; j++) hh2[j] = pk2(hs[2*j], hs[2*j+1]);
        }
        float* hrow = &sH[(size_t)(c * SPAT + dg) * 18];
#pragma unroll
        for (int j = 0; j < 8; j++) {
            float2 hv = upk2(hh2[j]);
            hrow[2*j] = hv.x; hrow[2*j+1] = hv.y;
        }
        sS[c * 128 + dg] = S;
    }
    __syncthreads();

    if (act && c == 0) {
        for (int cc = 1; cc < NCHUNK - 1; cc++) {
            float Sc = sS[cc * 128 + dg];
            float* cur = &sH[(size_t)(cc * SPAT + dg) * 18];
            float* prv = &sH[(size_t)((cc - 1) * SPAT + dg) * 18];
            if (geo) {
                float p1 = __expf(Sc * a1);
                float e = 1.f;
#pragma unroll
                for (int n = 0; n < NST; n++) {
                    e *= p1;
                    cur[n] += e * prv[n];
                }
            } else {
#pragma unroll
                for (int n = 0; n < NST; n++) {
                    float e = __expf(Sc * __ldg(&arow[n]));
                    cur[n] += e * prv[n];
                }
            }
        }
    }
    __syncthreads();

    if (act) {
        ull hh2[8];
        if (c == 0) {
#pragma unroll
            for (int j = 0; j < 8; j++) hh2[j] = pk2(0.f, 0.f);
        } else {
            const float* hrow = &sH[(size_t)((c - 1) * SPAT + dg) * 18];
#pragma unroll
            for (int j = 0; j < 8; j++) hh2[j] = pk2(hrow[2*j], hrow[2*j+1]);
        }
        float* yptr = ys + ((size_t)k * BL + (size_t)b * DI) * SPAT + dg;
        if (geo) {
            float dc = dptr[(size_t)l_beg * SPP];
            float uc = uptr[(size_t)l_beg * SPP];
            for (int l = l_beg; l < l_end; l++) {
                float d = dc, uv = uc;
                if (l + 1 < l_end) {
                    dc = dptr[(size_t)(l + 1) * SPP];
                    uc = uptr[(size_t)(l + 1) * SPP];
                }
                float du = d * uv;
                float q1 = __expf(d * a1);
                float q2 = q1 * q1;
                ull e2 = pk2(q1, q2), qq = pk2(q2, q2), du2 = pk2(du, du);
                ull yacc = pk2(0.f, 0.f);
                const float4* B4 = (const float4*)&sB[l * NST];
                const float4* C4 = (const float4*)&sC[l * NST];
#pragma unroll
                for (int jj = 0; jj < 4; jj++) {
                    float4 bb = B4[jj];
                    float4 cv = C4[jj];
                    hh2[2*jj]   = fma2(e2, hh2[2*jj],   mul2(du2, pk2(bb.x, bb.y)));
                    yacc        = fma2(hh2[2*jj], pk2(cv.x, cv.y), yacc);
                    e2 = mul2(e2, qq);
                    hh2[2*jj+1] = fma2(e2, hh2[2*jj+1], mul2(du2, pk2(bb.z, bb.w)));
                    yacc        = fma2(hh2[2*jj+1], pk2(cv.z, cv.w), yacc);
                    e2 = mul2(e2, qq);
                }
                float2 yv = upk2(yacc);
                yptr[(size_t)l * SPAT] = yv.x + yv.y + Dv * uv;
            }
        } else {
            float hs[NST];
#pragma unroll
            for (int j = 0; j < 8; j++) {
                float2 hv = upk2(hh2[j]);
                hs[2*j] = hv.x; hs[2*j+1] = hv.y;
            }
            for (int l = l_beg; l < l_end; l++) {
                float d  = dptr[(size_t)l * SPP];
                float uv = uptr[(size_t)l * SPP];
                float du = d * uv;
                float y = 0.f;
#pragma unroll
                for (int n = 0; n < NST; n++) {
                    float e = __expf(d * __ldg(&arow[n]));
                    hs[n] = e * hs[n] + du * sB[l * NST + n];
                    y += hs[n] * sC[l * NST + n];
                }
                yptr[(size_t)l * SPAT] = y + Dv * uv;
            }
        }
    }
}

// ---------------- combine dirs + LayerNorm(dg) + gelu(z) gate; write [b][dg][l] ----------------
__global__ void __launch_bounds__(256) ln_kernel(
    const float* __restrict__ ys, const float* __restrict__ xz,
    const float* __restrict__ ln_g, const float* __restrict__ ln_b,
    float* __restrict__ ygT)
{
    __shared__ float tY[64 * 129];
    __shared__ float s_mu[64], s_rs[64];

    int lt = blockIdx.x;
    int b  = blockIdx.y;
    int t  = threadIdx.x;

    const float* ysA = ys + ((size_t)b * DI + lt * 64) * SPAT;
    const float* ysB = ys + (size_t)BL * SPAT + (size_t)b * DI * SPAT;

    for (int idx = t; idx < 64 * SPAT; idx += 256) {
        int l = idx / SPAT, dg = idx - l * SPAT;
        int gl = lt * 64 + l;
        float v = ysA[(size_t)l * SPAT + dg] + ysB[(size_t)(255 - gl) * SPAT + dg];
        tY[l * 129 + dg] = v;
    }
    __syncthreads();

    int w = t >> 5, lane = t & 31;
    for (int l = w * 8; l < w * 8 + 8; l++) {
        float s1 = 0.f, s2 = 0.f;
        for (int dg = lane; dg < SPAT; dg += 32) {
            float v = tY[l * 129 + dg];
            s1 += v; s2 += v * v;
        }
#pragma unroll
        for (int off = 16; off > 0; off >>= 1) {
            s1 += __shfl_xor_sync(0xffffffffu, s1, off);
            s2 += __shfl_xor_sync(0xffffffffu, s2, off);
        }
        if (lane == 0) {
            float mu = s1 * (1.f / SPAT);
            float var = s2 * (1.f / SPAT) - mu * mu;
            s_mu[l] = mu;
            s_rs[l] = rsqrtf(var + 1e-5f);
        }
    }
    __syncthreads();

    for (int idx = t; idx < SPAT * 64; idx += 256) {
        int dg = idx >> 6, l = idx & 63;
        int gl = lt * 64 + l;
        float v = (tY[l * 129 + dg] - s_mu[l]) * s_rs[l] * ln_g[dg] + ln_b[dg];
        float zv = xz[((size_t)b * SPAT + dg) * 512 + 256 + gl];
        float gz = 0.5f * zv * (1.f + erff(zv * 0.7071067811865475f));
        ygT[((size_t)b * SPAT + dg) * DI + gl] = v * gz;
    }
}

// ---------------- launcher ----------------
extern "C" void kernel_launch(void* const* d_in, const int* in_sizes, int n_in,
                              void* d_out, int out_size)
{
    const float* x         = (const float*)d_in[0];
    const float* in_proj_w = (const float*)d_in[1];
    const float* conv_w    = (const float*)d_in[2];
    const float* conv_b    = (const float*)d_in[3];
    const float* x_proj_w  = (const float*)d_in[4];
    const float* dt_proj_w = (const float*)d_in[5];
    const float* dt_proj_b = (const float*)d_in[6];
    const float* A_logs    = (const float*)d_in[7];
    const float* Ds        = (const float*)d_in[8];
    const float* ln_g      = (const float*)d_in[9];
    const float* ln_b      = (const float*)d_in[10];
    const float* out_proj_w= (const float*)d_in[11];
    float* out = (float*)d_out;

    float *p_xz, *p_u, *p_xw, *p_xdbl2, *p_delta, *p_ys, *p_ygT;
    cudaGetSymbolAddress((void**)&p_xz,    g_xz);
    cudaGetSymbolAddress((void**)&p_u,     g_u);
    cudaGetSymbolAddress((void**)&p_xw,    g_xw);
    cudaGetSymbolAddress((void**)&p_xdbl2, g_xdbl2);
    cudaGetSymbolAddress((void**)&p_delta, g_delta);
    cudaGetSymbolAddress((void**)&p_ys,    g_ys);
    cudaGetSymbolAddress((void**)&p_ygT,   g_ygT);

    cudaFuncSetAttribute(scan_kernel,
                         cudaFuncAttributeMaxDynamicSharedMemorySize,
                         SCAN_SMEM_BYTES);
    cudaFuncSetAttribute(gemm_tc,
                         cudaFuncAttributeMaxDynamicSharedMemorySize,
                         GT_SMEM_BYTES);

    // K0: pack x_proj_w into padded [80][128]
    pack_w_kernel<<<(C80 * SPP + 255) / 256, 256>>>(x_proj_w, p_xw);

    // K1: xz = x @ in_proj_w.T   [15488,128] x [512,128]^T
    gemm_tc<<<dim3(ROWS / 128, 4), 256, GT_SMEM_BYTES>>>(
        x, in_proj_w, p_xz, 512, DM, DM, DM, 512);

    // K2: depthwise conv + SiLU -> u[b][l][dg] (stride 128, zero-padded)
    conv_kernel<<<dim3(4, BATCH), 256>>>(p_xz, conv_w, conv_b, p_u);

    // K3: merged x_dbl: [32768,128pad] x [80,128pad]^T -> [32768,80]
    gemm_tc<<<dim3(BL / 128, 1), 256, GT_SMEM_BYTES>>>(
        p_u, p_xw, p_xdbl2, C80, SPP, SPP, SPP, C80);

    // K3b: delta = fast-softplus(dt-proj)
    delta_kernel<<<dim3(BATCH, 2), 512>>>(p_xdbl2, dt_proj_w, dt_proj_b, p_delta);

    // K4: chunk-parallel selective scan (f32x2 + prefetch)
    scan_kernel<<<dim3(BATCH, 2), 512, SCAN_SMEM_BYTES>>>(
        p_xdbl2, p_u, p_delta, A_logs, Ds, p_ys);

    // K5: combine directions + LN + gelu(z) gate -> ygT[b*121+dg][l]
    ln_kernel<<<dim3(4, BATCH), 256>>>(p_ys, p_xz, ln_g, ln_b, p_ygT);

    // K6: out = ygT @ out_proj_w.T   [15488,256] x [128,256]^T
    gemm_tc<<<dim3(ROWS / 128, 1), 256, GT_SMEM_BYTES>>>(
        p_ygT, out_proj_w, out, DM, DI, DI, DI, DM);
}